// round 13
// baseline (speedup 1.0000x reference)
#include <cuda_runtime.h>

#define NMAX 100000
#define CAP  64            // max in-degree bucketed (Poisson(16); P(>64) ~ 1e-20)

// ---------------- scratch (device globals: no allocs allowed) ----------------
// g_cnt is zero at module load; agg2_kernel re-zeroes it each run after use.
__device__ float g_h1 [NMAX * 64];
__device__ float g_h1o[NMAX * 64];
__device__ float g_h2 [NMAX * 64];
__device__ float g_es1[NMAX * 8];
__device__ float g_ed1[NMAX * 8];
__device__ float g_es2[NMAX];
__device__ float g_ed2[NMAX];
__device__ int   g_cnt[NMAX];
__device__ int   g_csrc[NMAX * CAP];
__device__ int   g_is64;

typedef unsigned long long u64;

__device__ __forceinline__ u64 pack2(float lo, float hi) {
    u64 r; asm("mov.b64 %0, {%1, %2};" : "=l"(r) : "f"(lo), "f"(hi)); return r;
}
__device__ __forceinline__ void unpack2(u64 v, float& lo, float& hi) {
    asm("mov.b64 {%0, %1}, %2;" : "=f"(lo), "=f"(hi) : "l"(v));
}
__device__ __forceinline__ u64 ffma2(u64 a, u64 b, u64 c) {
    u64 d; asm("fma.rn.f32x2 %0, %1, %2, %3;" : "=l"(d) : "l"(a), "l"(b), "l"(c)); return d;
}
__device__ __forceinline__ float lrelu(float t) { return t > 0.f ? t : 0.2f * t; }

// ---------------- edge dtype probe (one tiny launch) ----------------
// little-endian int64 node ids (<2^31) have zero odd 32-bit words
__global__ void probe_kernel(const int* __restrict__ ei) {
    if (threadIdx.x == 0) {
        int all_zero = 1;
        for (int k = 1; k < 64; k += 2)
            if (ei[k] != 0) all_zero = 0;
        g_is64 = all_zero;
    }
}

// ---------------- direct binning: one edge pass, no count/scan ----------------
__global__ void scatter_kernel(const int* __restrict__ ei, int E, int N,
                               int base, int cnt_this)
{
    int i = blockIdx.x * blockDim.x + threadIdx.x;
    if (i >= cnt_this) return;
    int e = base + i;
    int dst, src;
    if (g_is64) { dst = ei[2 * (E + e)]; src = ei[2 * e]; }
    else        { dst = ei[E + e];       src = ei[e]; }
    if ((unsigned)dst >= (unsigned)N) return;
    int pos = atomicAdd(&g_cnt[dst], 1);
    if (pos < CAP) g_csrc[dst * CAP + pos] = src;
}

// ---------------- GEMM tile: 32 nodes x 64 cols x LEN k-values ----------------
// Warp layout: warp w -> column half ch=w&1 (32 cols, lane=col), row quarter
// rq=w>>1 (8 rows). Per 2 k-pairs: 2 weight LDS.64 + 8 broadcast x LDS.128
// feed 16 FFMA2 (f32x2 packed over k).
template <int LEN, int K>
__device__ __forceinline__ void gemm_tile(const float* __restrict__ X,
                                          const float* __restrict__ W,
                                          float (*xs)[64], u64 (*ws2)[64],
                                          int n0, int k0, int N,
                                          int ch, int rq, int lane, u64* acc)
{
    // X tile load: r = tid>>3 (32 rows), lg = tid&7, float4 strided — no division
    {
        int r  = threadIdx.x >> 3;
        int lg = threadIdx.x & 7;
        int n  = n0 + r;
#pragma unroll
        for (int q = 0; q < 2; q++) {
            int c4 = lg * 4 + q * 32;                  // 0..60
            float4 v = make_float4(0.f, 0.f, 0.f, 0.f);
            if (c4 < LEN && n < N)
                v = *reinterpret_cast<const float4*>(&X[(size_t)n * K + k0 + c4]);
            *reinterpret_cast<float4*>(&xs[r][c4]) = v;
        }
    }
    // W pair pack: (LEN/2) x 64
    for (int i = threadIdx.x; i < (LEN / 2) * 64; i += 256) {
        int kk2 = i >> 6, c = i & 63;
        float w0 = W[(size_t)(k0 + 2 * kk2) * 64 + c];
        float w1 = W[(size_t)(k0 + 2 * kk2 + 1) * 64 + c];
        ws2[kk2][c] = pack2(w0, w1);
    }
    __syncthreads();
#pragma unroll 4
    for (int kk2 = 0; kk2 < LEN / 2; kk2 += 2) {
        u64 w0 = ws2[kk2][ch * 32 + lane];
        u64 w1 = ws2[kk2 + 1][ch * 32 + lane];
#pragma unroll
        for (int j = 0; j < 8; j++) {
            ulonglong2 xv = *reinterpret_cast<const ulonglong2*>(&xs[rq * 8 + j][kk2 * 2]);
            acc[j] = ffma2(xv.x, w0, acc[j]);
            acc[j] = ffma2(xv.y, w1, acc[j]);
        }
    }
    __syncthreads();
}

// ---------------- GEMM + fused attention logits epilogue ----------------
template <int K, int HEADS>
__global__ __launch_bounds__(256, 5)
void gemm_att_kernel(const float* __restrict__ X, const float* __restrict__ W,
                     float* __restrict__ H,
                     const float* __restrict__ as, const float* __restrict__ ad,
                     float* __restrict__ es, float* __restrict__ ed, int N)
{
    __shared__ __align__(16) float xs[32][64];     // 8 KB (reused for output tile)
    __shared__ u64 ws2[32][64];                    // 16 KB
    const int n0   = blockIdx.x * 32;
    const int lane = threadIdx.x & 31;
    const int w    = threadIdx.x >> 5;
    const int ch   = w & 1;                        // column half
    const int rq   = w >> 1;                       // row quarter

    u64 acc[8];
#pragma unroll
    for (int j = 0; j < 8; j++) acc[j] = 0ull;

    if (K == 300) {
        gemm_tile<64, K>(X, W, xs, ws2, n0,   0, N, ch, rq, lane, acc);
        gemm_tile<64, K>(X, W, xs, ws2, n0,  64, N, ch, rq, lane, acc);
        gemm_tile<64, K>(X, W, xs, ws2, n0, 128, N, ch, rq, lane, acc);
        gemm_tile<64, K>(X, W, xs, ws2, n0, 192, N, ch, rq, lane, acc);
        gemm_tile<44, K>(X, W, xs, ws2, n0, 256, N, ch, rq, lane, acc);
    } else {
        gemm_tile<64, K>(X, W, xs, ws2, n0, 0, N, ch, rq, lane, acc);
    }

    // stage the 32x64 output tile back into xs, write H
    const int c = ch * 32 + lane;
#pragma unroll
    for (int j = 0; j < 8; j++) {
        int r = rq * 8 + j;
        int n = n0 + r;
        float lo, hi; unpack2(acc[j], lo, hi);
        float v = lo + hi;
        xs[r][c] = v;
        if (n < N) H[(size_t)n * 64 + c] = v;
    }
    __syncthreads();

    // attention logits from shared tile
    if (HEADS == 8) {
        int p = threadIdx.x;                 // 256 = 32 nodes x 8 heads
        int r = p >> 3, hh = p & 7;
        int n = n0 + r;
        if (n < N) {
            float s = 0.f, d = 0.f;
#pragma unroll
            for (int k = 0; k < 8; k++) {
                float v = xs[r][hh * 8 + k];
                s += v * as[hh * 8 + k];
                d += v * ad[hh * 8 + k];
            }
            es[n * 8 + hh] = s;
            ed[n * 8 + hh] = d;
        }
    } else {
        int r = threadIdx.x >> 3, part = threadIdx.x & 7;  // 32 nodes x 8 parts
        float s = 0.f, d = 0.f;
#pragma unroll
        for (int k = 0; k < 8; k++) {
            float v = xs[r][part * 8 + k];
            s += v * as[part * 8 + k];
            d += v * ad[part * 8 + k];
        }
        s += __shfl_xor_sync(0xffffffffu, s, 1);
        s += __shfl_xor_sync(0xffffffffu, s, 2);
        s += __shfl_xor_sync(0xffffffffu, s, 4);
        d += __shfl_xor_sync(0xffffffffu, d, 1);
        d += __shfl_xor_sync(0xffffffffu, d, 2);
        d += __shfl_xor_sync(0xffffffffu, d, 4);
        int n = n0 + r;
        if (part == 0 && n < N) { es[n] = s; ed[n] = d; }
    }
}

// ---------------- layer-1 aggregation (float2 lanes, unroll x8) ----------------
__global__ void agg1_kernel(const float* __restrict__ H, const float* __restrict__ bias,
                            float* __restrict__ O, int N)
{
    int g = blockIdx.x * blockDim.x + threadIdx.x;
    int n = g >> 5, lane = g & 31;
    if (n >= N) return;
    const float2* __restrict__ H2 = reinterpret_cast<const float2*>(H);
    int hh = lane >> 2;
    float edv = g_ed1[n * 8 + hh];

    // self-loop (PyG default add_self_loops)
    float w = __expf(lrelu(g_es1[n * 8 + hh] + edv));
    float ws = w;
    float2 hv = H2[n * 32 + lane];
    float accx = w * hv.x, accy = w * hv.y;

    int cnt = g_cnt[n];
    if (cnt > CAP) cnt = CAP;
    int e  = n * CAP, e1 = n * CAP + cnt;
    for (; e + 8 <= e1; e += 8) {
        int s0 = g_csrc[e],     s1 = g_csrc[e + 1], s2 = g_csrc[e + 2], s3 = g_csrc[e + 3];
        int s4 = g_csrc[e + 4], s5 = g_csrc[e + 5], s6 = g_csrc[e + 6], s7 = g_csrc[e + 7];
        float a0 = g_es1[s0 * 8 + hh], a1 = g_es1[s1 * 8 + hh];
        float a2 = g_es1[s2 * 8 + hh], a3 = g_es1[s3 * 8 + hh];
        float a4 = g_es1[s4 * 8 + hh], a5 = g_es1[s5 * 8 + hh];
        float a6 = g_es1[s6 * 8 + hh], a7 = g_es1[s7 * 8 + hh];
        float2 h0 = H2[s0 * 32 + lane], h1v = H2[s1 * 32 + lane];
        float2 h2v = H2[s2 * 32 + lane], h3 = H2[s3 * 32 + lane];
        float2 h4 = H2[s4 * 32 + lane], h5 = H2[s5 * 32 + lane];
        float2 h6 = H2[s6 * 32 + lane], h7 = H2[s7 * 32 + lane];
        float x0 = __expf(lrelu(a0 + edv)), x1 = __expf(lrelu(a1 + edv));
        float x2 = __expf(lrelu(a2 + edv)), x3 = __expf(lrelu(a3 + edv));
        float x4 = __expf(lrelu(a4 + edv)), x5 = __expf(lrelu(a5 + edv));
        float x6 = __expf(lrelu(a6 + edv)), x7 = __expf(lrelu(a7 + edv));
        ws += ((x0 + x1) + (x2 + x3)) + ((x4 + x5) + (x6 + x7));
        accx = fmaf(x0, h0.x,  accx); accy = fmaf(x0, h0.y,  accy);
        accx = fmaf(x1, h1v.x, accx); accy = fmaf(x1, h1v.y, accy);
        accx = fmaf(x2, h2v.x, accx); accy = fmaf(x2, h2v.y, accy);
        accx = fmaf(x3, h3.x,  accx); accy = fmaf(x3, h3.y,  accy);
        accx = fmaf(x4, h4.x,  accx); accy = fmaf(x4, h4.y,  accy);
        accx = fmaf(x5, h5.x,  accx); accy = fmaf(x5, h5.y,  accy);
        accx = fmaf(x6, h6.x,  accx); accy = fmaf(x6, h6.y,  accy);
        accx = fmaf(x7, h7.x,  accx); accy = fmaf(x7, h7.y,  accy);
    }
    for (; e < e1; e++) {
        int s = g_csrc[e];
        float x = __expf(lrelu(g_es1[s * 8 + hh] + edv));
        float2 hv2 = H2[s * 32 + lane];
        ws += x;
        accx = fmaf(x, hv2.x, accx);
        accy = fmaf(x, hv2.y, accy);
    }
    float2 bv = reinterpret_cast<const float2*>(bias)[lane];
    float ox = accx / ws + bv.x;
    float oy = accy / ws + bv.y;
    float2 ov;
    ov.x = ox > 0.f ? ox : (__expf(ox) - 1.f);   // ELU
    ov.y = oy > 0.f ? oy : (__expf(oy) - 1.f);
    reinterpret_cast<float2*>(O)[n * 32 + lane] = ov;
}

// ---------------- layer-2 aggregation + bias + log_softmax -> d_out ----------------
// Also re-zeroes g_cnt[n] so the next graph replay starts from clean state.
__global__ void agg2_kernel(const float* __restrict__ H, const float* __restrict__ bias,
                            float* __restrict__ O, int N)
{
    int g = blockIdx.x * blockDim.x + threadIdx.x;
    int n = g >> 5, lane = g & 31;
    if (n >= N) return;
    const float2* __restrict__ H2 = reinterpret_cast<const float2*>(H);
    float edn = g_ed2[n];

    float w  = __expf(lrelu(g_es2[n] + edn));   // self-loop
    float ws = w;
    float2 hv = H2[n * 32 + lane];
    float accx = w * hv.x, accy = w * hv.y;

    int cnt = g_cnt[n];
    if (cnt > CAP) cnt = CAP;
    if (lane == 0) g_cnt[n] = 0;                 // reset for next replay
    int e  = n * CAP, e1 = n * CAP + cnt;
    for (; e + 8 <= e1; e += 8) {
        int s0 = g_csrc[e],     s1 = g_csrc[e + 1], s2 = g_csrc[e + 2], s3 = g_csrc[e + 3];
        int s4 = g_csrc[e + 4], s5 = g_csrc[e + 5], s6 = g_csrc[e + 6], s7 = g_csrc[e + 7];
        float a0 = g_es2[s0], a1 = g_es2[s1], a2 = g_es2[s2], a3 = g_es2[s3];
        float a4 = g_es2[s4], a5 = g_es2[s5], a6 = g_es2[s6], a7 = g_es2[s7];
        float2 h0 = H2[s0 * 32 + lane], h1v = H2[s1 * 32 + lane];
        float2 h2v = H2[s2 * 32 + lane], h3 = H2[s3 * 32 + lane];
        float2 h4 = H2[s4 * 32 + lane], h5 = H2[s5 * 32 + lane];
        float2 h6 = H2[s6 * 32 + lane], h7 = H2[s7 * 32 + lane];
        float x0 = __expf(lrelu(a0 + edn)), x1 = __expf(lrelu(a1 + edn));
        float x2 = __expf(lrelu(a2 + edn)), x3 = __expf(lrelu(a3 + edn));
        float x4 = __expf(lrelu(a4 + edn)), x5 = __expf(lrelu(a5 + edn));
        float x6 = __expf(lrelu(a6 + edn)), x7 = __expf(lrelu(a7 + edn));
        ws += ((x0 + x1) + (x2 + x3)) + ((x4 + x5) + (x6 + x7));
        accx = fmaf(x0, h0.x,  accx); accy = fmaf(x0, h0.y,  accy);
        accx = fmaf(x1, h1v.x, accx); accy = fmaf(x1, h1v.y, accy);
        accx = fmaf(x2, h2v.x, accx); accy = fmaf(x2, h2v.y, accy);
        accx = fmaf(x3, h3.x,  accx); accy = fmaf(x3, h3.y,  accy);
        accx = fmaf(x4, h4.x,  accx); accy = fmaf(x4, h4.y,  accy);
        accx = fmaf(x5, h5.x,  accx); accy = fmaf(x5, h5.y,  accy);
        accx = fmaf(x6, h6.x,  accx); accy = fmaf(x6, h6.y,  accy);
        accx = fmaf(x7, h7.x,  accx); accy = fmaf(x7, h7.y,  accy);
    }
    for (; e < e1; e++) {
        int s = g_csrc[e];
        float x = __expf(lrelu(g_es2[s] + edn));
        float2 hv2 = H2[s * 32 + lane];
        ws += x;
        accx = fmaf(x, hv2.x, accx);
        accy = fmaf(x, hv2.y, accy);
    }
    float2 bv = reinterpret_cast<const float2*>(bias)[lane];
    float vA = accx / ws + bv.x;
    float vB = accy / ws + bv.y;

    // log_softmax over 64 columns (2 per lane)
    float mx = fmaxf(vA, vB);
#pragma unroll
    for (int o = 16; o; o >>= 1) mx = fmaxf(mx, __shfl_xor_sync(0xffffffffu, mx, o));
    float se = __expf(vA - mx) + __expf(vB - mx);
#pragma unroll
    for (int o = 16; o; o >>= 1) se += __shfl_xor_sync(0xffffffffu, se, o);
    float lse = mx + logf(se);
    float2 ov; ov.x = vA - lse; ov.y = vB - lse;
    reinterpret_cast<float2*>(O)[n * 32 + lane] = ov;
}

// ---------------- launch ----------------
// Order: probe(0) scatterA(1) scatterB(2) gemm1(3) agg1(4) gemm2(5) agg2(6)
// -> ncu (-s 5, 2 hidden harness launches) captures the NEW gemm1.
extern "C" void kernel_launch(void* const* d_in, const int* in_sizes, int n_in,
                              void* d_out, int out_size)
{
    const float* x   = (const float*)d_in[0];
    const int*   ei  = (const int*)d_in[1];    // int32 OR int64 (probed)
    const float* W1  = (const float*)d_in[2];
    const float* as1 = (const float*)d_in[3];
    const float* ad1 = (const float*)d_in[4];
    const float* b1  = (const float*)d_in[5];
    const float* W2  = (const float*)d_in[6];
    const float* as2 = (const float*)d_in[7];
    const float* ad2 = (const float*)d_in[8];
    const float* b2  = (const float*)d_in[9];

    const int N = in_sizes[0] / 300;
    const int E = in_sizes[1] / 2;
    float* out = (float*)d_out;

    void *ph1, *ph1o, *ph2, *pes1, *ped1, *pes2, *ped2;
    cudaGetSymbolAddress(&ph1,  g_h1);
    cudaGetSymbolAddress(&ph1o, g_h1o);
    cudaGetSymbolAddress(&ph2,  g_h2);
    cudaGetSymbolAddress(&pes1, g_es1);
    cudaGetSymbolAddress(&ped1, g_ed1);
    cudaGetSymbolAddress(&pes2, g_es2);
    cudaGetSymbolAddress(&ped2, g_ed2);
    float* h1  = (float*)ph1;
    float* h1o = (float*)ph1o;
    float* h2  = (float*)ph2;

    const int tb = 256;
    const int G1 = (N + 31) / 32;
    const int Eh = E / 2;

    // direct-binned CSR (no count/scan)
    probe_kernel  <<<1, 32>>>(ei);
    scatter_kernel<<<(Eh + tb - 1) / tb, tb>>>(ei, E, N, 0, Eh);
    scatter_kernel<<<((E - Eh) + tb - 1) / tb, tb>>>(ei, E, N, Eh, E - Eh);

    // layer 1
    gemm_att_kernel<300, 8><<<G1, 256>>>(x, W1, h1, as1, ad1,
                                         (float*)pes1, (float*)ped1, N);
    agg1_kernel<<<(N + 7) / 8, tb>>>(h1, b1, h1o, N);

    // layer 2
    gemm_att_kernel<64, 1><<<G1, 256>>>(h1o, W2, h2, as2, ad2,
                                        (float*)pes2, (float*)ped2, N);
    agg2_kernel<<<(N + 7) / 8, tb>>>(h2, b2, out, N);
}

// round 14
// speedup vs baseline: 1.5666x; 1.5666x over previous
#include <cuda_runtime.h>

#define NMAX 100000
#define EMAX 1600000

// ---------------- scratch (device globals: no allocs allowed) ----------------
// g_deg is zero at module load; scanBC_kernel re-zeroes it after use each run.
__device__ float g_h1 [NMAX * 64];
__device__ float g_h1o[NMAX * 64];
__device__ float g_h2 [NMAX * 64];
__device__ float g_es1[NMAX * 8];
__device__ float g_ed1[NMAX * 8];
__device__ float g_es2[NMAX];
__device__ float g_ed2[NMAX];
__device__ int   g_deg[NMAX];
__device__ int   g_rowptr [NMAX + 1];
__device__ int   g_rowptr2[NMAX];      // bump cursors for scatter
__device__ int   g_csrc[EMAX];
__device__ int   g_blocksum[1024];

typedef unsigned long long u64;

__device__ __forceinline__ u64 pack2(float lo, float hi) {
    u64 r; asm("mov.b64 %0, {%1, %2};" : "=l"(r) : "f"(lo), "f"(hi)); return r;
}
__device__ __forceinline__ void unpack2(u64 v, float& lo, float& hi) {
    asm("mov.b64 {%0, %1}, %2;" : "=f"(lo), "=f"(hi) : "l"(v));
}
__device__ __forceinline__ u64 ffma2(u64 a, u64 b, u64 c) {
    u64 d; asm("fma.rn.f32x2 %0, %1, %2, %3;" : "=l"(d) : "l"(a), "l"(b), "l"(c)); return d;
}
__device__ __forceinline__ float lrelu(float t) { return t > 0.f ? t : 0.2f * t; }

// per-block edge-dtype probe: little-endian int64 ids (<2^31) have zero odd words
__device__ __forceinline__ int probe_is64_block(const int* __restrict__ ei, int* s_flag) {
    if (threadIdx.x == 0) {
        int all_zero = 1;
        for (int k = 1; k < 64; k += 2)
            if (ei[k] != 0) all_zero = 0;
        *s_flag = all_zero;
    }
    __syncthreads();
    return *s_flag;
}

// ---------------- CSR build ----------------
__global__ void count_kernel(const int* __restrict__ ei, int E, int N) {
    __shared__ int s_flag;
    int is64 = probe_is64_block(ei, &s_flag);
    int e = blockIdx.x * blockDim.x + threadIdx.x;
    if (e < E) {
        int dst = is64 ? ei[2 * (E + e)] : ei[E + e];
        if ((unsigned)dst < (unsigned)N) atomicAdd(&g_deg[dst], 1);
    }
}

// hierarchical scan, phase A: per-block degree sums (391 parallel blocks)
__global__ void scanA_kernel(int N) {
    __shared__ int red[256];
    int i = blockIdx.x * 256 + threadIdx.x;
    red[threadIdx.x] = (i < N) ? g_deg[i] : 0;
    __syncthreads();
    for (int off = 128; off; off >>= 1) {
        if (threadIdx.x < off) red[threadIdx.x] += red[threadIdx.x + off];
        __syncthreads();
    }
    if (threadIdx.x == 0) g_blocksum[blockIdx.x] = red[0];
}

// phase BC: block b sums blocksum[0..b), local exclusive scan, writes rowptr +
// bump cursors, re-zeroes g_deg for the next graph replay.
__global__ void scanBC_kernel(int N) {
    __shared__ int ps[256];
    int b = blockIdx.x, t = threadIdx.x;

    // offset = sum of blocksum[0..b)
    int part = 0;
    for (int j = t; j < b; j += 256) part += g_blocksum[j];
    ps[t] = part;
    __syncthreads();
    for (int off = 128; off; off >>= 1) {
        if (t < off) ps[t] += ps[t + off];
        __syncthreads();
    }
    int offset = ps[0];
    __syncthreads();

    // local exclusive scan of this block's 256 degrees
    int i = b * 256 + t;
    int d = (i < N) ? g_deg[i] : 0;
    ps[t] = d;
    __syncthreads();
    for (int off = 1; off < 256; off <<= 1) {
        int v = (t >= off) ? ps[t - off] : 0;
        __syncthreads();
        ps[t] += v;
        __syncthreads();
    }
    int ex = offset + ps[t] - d;
    if (i < N) {
        g_rowptr[i]  = ex;
        g_rowptr2[i] = ex;
        g_deg[i]     = 0;
    }
    if (i == N - 1) g_rowptr[N] = ex + d;
}

__global__ void scatter_kernel(const int* __restrict__ ei, int E, int N) {
    __shared__ int s_flag;
    int is64 = probe_is64_block(ei, &s_flag);
    int e = blockIdx.x * blockDim.x + threadIdx.x;
    if (e < E) {
        int dst, src;
        if (is64) { dst = ei[2 * (E + e)]; src = ei[2 * e]; }
        else      { dst = ei[E + e];       src = ei[e]; }
        if ((unsigned)dst >= (unsigned)N) return;
        int pos = atomicAdd(&g_rowptr2[dst], 1);
        if ((unsigned)pos < (unsigned)EMAX) g_csrc[pos] = src;
    }
}

// ---------------- GEMM + fused attention logits epilogue (R9 version) ----------------
template <int K, int HEADS>
__global__ __launch_bounds__(128)
void gemm_att_kernel(const float* __restrict__ X, const float* __restrict__ W,
                     float* __restrict__ H,
                     const float* __restrict__ as, const float* __restrict__ ad,
                     float* __restrict__ es, float* __restrict__ ed, int N)
{
    constexpr int KT = 64;
    __shared__ __align__(16) float xs[32][KT];     // 8 KB (reused for output tile)
    __shared__ u64 ws2[KT / 2][64];                // 16 KB: (W[k],W[k+1]) per col
    const int n0   = blockIdx.x * 32;
    const int cb   = threadIdx.x & 31;             // cols cb and cb+32
    const int slot = threadIdx.x >> 5;             // 4 slots x 8 nodes

    u64 accA[8], accB[8];
#pragma unroll
    for (int j = 0; j < 8; j++) { accA[j] = 0ull; accB[j] = 0ull; }

    for (int k0 = 0; k0 < K; k0 += KT) {
        const int len = (K - k0 < KT) ? (K - k0) : KT;   // 64 or 44; len/2 always even
        for (int i = threadIdx.x; i < 32 * len; i += 128) {
            int r = i / len, c = i - r * len;
            int n = n0 + r;
            xs[r][c] = (n < N) ? X[(size_t)n * K + k0 + c] : 0.f;
        }
        for (int i = threadIdx.x; i < (len / 2) * 64; i += 128) {
            int kk2 = i >> 6, c = i & 63;
            float w0 = W[(size_t)(k0 + 2 * kk2) * 64 + c];
            float w1 = W[(size_t)(k0 + 2 * kk2 + 1) * 64 + c];
            ws2[kk2][c] = pack2(w0, w1);
        }
        __syncthreads();
        const int len2 = len >> 1;
        for (int kk2 = 0; kk2 < len2; kk2 += 2) {
            u64 wA0 = ws2[kk2][cb],     wB0 = ws2[kk2][cb + 32];
            u64 wA1 = ws2[kk2 + 1][cb], wB1 = ws2[kk2 + 1][cb + 32];
#pragma unroll
            for (int j = 0; j < 8; j++) {
                ulonglong2 xv = *reinterpret_cast<const ulonglong2*>(&xs[slot * 8 + j][kk2 * 2]);
                accA[j] = ffma2(xv.x, wA0, accA[j]);
                accB[j] = ffma2(xv.x, wB0, accB[j]);
                accA[j] = ffma2(xv.y, wA1, accA[j]);
                accB[j] = ffma2(xv.y, wB1, accB[j]);
            }
        }
        __syncthreads();
    }

    // stage the 32x64 output tile back into xs, write H
#pragma unroll
    for (int j = 0; j < 8; j++) {
        int r = slot * 8 + j;
        int n = n0 + r;
        float a0, a1, b0, b1;
        unpack2(accA[j], a0, a1);
        unpack2(accB[j], b0, b1);
        float vA = a0 + a1, vB = b0 + b1;
        xs[r][cb] = vA; xs[r][cb + 32] = vB;
        if (n < N) {
            H[(size_t)n * 64 + cb]      = vA;
            H[(size_t)n * 64 + cb + 32] = vB;
        }
    }
    __syncthreads();

    // attention logits from shared tile
    if (HEADS == 8) {
        for (int p = threadIdx.x; p < 256; p += 128) {
            int r = p >> 3, hh = p & 7;
            int n = n0 + r;
            if (n < N) {
                float s = 0.f, d = 0.f;
#pragma unroll
                for (int k = 0; k < 8; k++) {
                    float v = xs[r][hh * 8 + k];
                    s += v * as[hh * 8 + k];
                    d += v * ad[hh * 8 + k];
                }
                es[n * 8 + hh] = s;
                ed[n * 8 + hh] = d;
            }
        }
    } else {
        int r = threadIdx.x >> 2, part = threadIdx.x & 3;
        float s = 0.f, d = 0.f;
#pragma unroll
        for (int k = 0; k < 16; k++) {
            float v = xs[r][part * 16 + k];
            s += v * as[part * 16 + k];
            d += v * ad[part * 16 + k];
        }
        s += __shfl_xor_sync(0xffffffffu, s, 1);
        s += __shfl_xor_sync(0xffffffffu, s, 2);
        d += __shfl_xor_sync(0xffffffffu, d, 1);
        d += __shfl_xor_sync(0xffffffffu, d, 2);
        int n = n0 + r;
        if (part == 0 && n < N) { es[n] = s; ed[n] = d; }
    }
}

// ---------------- layer-1 aggregation (float2 lanes, unroll x8) ----------------
__global__ void agg1_kernel(const float* __restrict__ H, const float* __restrict__ bias,
                            float* __restrict__ O, int N)
{
    int g = blockIdx.x * blockDim.x + threadIdx.x;
    int n = g >> 5, lane = g & 31;
    if (n >= N) return;
    const float2* __restrict__ H2 = reinterpret_cast<const float2*>(H);
    int hh = lane >> 2;
    float edv = g_ed1[n * 8 + hh];

    // self-loop (PyG default add_self_loops)
    float w = __expf(lrelu(g_es1[n * 8 + hh] + edv));
    float ws = w;
    float2 hv = H2[n * 32 + lane];
    float accx = w * hv.x, accy = w * hv.y;

    int e = g_rowptr[n], e1 = g_rowptr[n + 1];
    for (; e + 8 <= e1; e += 8) {
        int s0 = g_csrc[e],     s1 = g_csrc[e + 1], s2 = g_csrc[e + 2], s3 = g_csrc[e + 3];
        int s4 = g_csrc[e + 4], s5 = g_csrc[e + 5], s6 = g_csrc[e + 6], s7 = g_csrc[e + 7];
        float a0 = g_es1[s0 * 8 + hh], a1 = g_es1[s1 * 8 + hh];
        float a2 = g_es1[s2 * 8 + hh], a3 = g_es1[s3 * 8 + hh];
        float a4 = g_es1[s4 * 8 + hh], a5 = g_es1[s5 * 8 + hh];
        float a6 = g_es1[s6 * 8 + hh], a7 = g_es1[s7 * 8 + hh];
        float2 h0 = H2[s0 * 32 + lane], h1v = H2[s1 * 32 + lane];
        float2 h2v = H2[s2 * 32 + lane], h3 = H2[s3 * 32 + lane];
        float2 h4 = H2[s4 * 32 + lane], h5 = H2[s5 * 32 + lane];
        float2 h6 = H2[s6 * 32 + lane], h7 = H2[s7 * 32 + lane];
        float x0 = __expf(lrelu(a0 + edv)), x1 = __expf(lrelu(a1 + edv));
        float x2 = __expf(lrelu(a2 + edv)), x3 = __expf(lrelu(a3 + edv));
        float x4 = __expf(lrelu(a4 + edv)), x5 = __expf(lrelu(a5 + edv));
        float x6 = __expf(lrelu(a6 + edv)), x7 = __expf(lrelu(a7 + edv));
        ws += ((x0 + x1) + (x2 + x3)) + ((x4 + x5) + (x6 + x7));
        accx = fmaf(x0, h0.x,  accx); accy = fmaf(x0, h0.y,  accy);
        accx = fmaf(x1, h1v.x, accx); accy = fmaf(x1, h1v.y, accy);
        accx = fmaf(x2, h2v.x, accx); accy = fmaf(x2, h2v.y, accy);
        accx = fmaf(x3, h3.x,  accx); accy = fmaf(x3, h3.y,  accy);
        accx = fmaf(x4, h4.x,  accx); accy = fmaf(x4, h4.y,  accy);
        accx = fmaf(x5, h5.x,  accx); accy = fmaf(x5, h5.y,  accy);
        accx = fmaf(x6, h6.x,  accx); accy = fmaf(x6, h6.y,  accy);
        accx = fmaf(x7, h7.x,  accx); accy = fmaf(x7, h7.y,  accy);
    }
    for (; e < e1; e++) {
        int s = g_csrc[e];
        float x = __expf(lrelu(g_es1[s * 8 + hh] + edv));
        float2 hv2 = H2[s * 32 + lane];
        ws += x;
        accx = fmaf(x, hv2.x, accx);
        accy = fmaf(x, hv2.y, accy);
    }
    float2 bv = reinterpret_cast<const float2*>(bias)[lane];
    float ox = accx / ws + bv.x;
    float oy = accy / ws + bv.y;
    float2 ov;
    ov.x = ox > 0.f ? ox : (__expf(ox) - 1.f);   // ELU
    ov.y = oy > 0.f ? oy : (__expf(oy) - 1.f);
    reinterpret_cast<float2*>(O)[n * 32 + lane] = ov;
}

// ---------------- layer-2 aggregation + bias + log_softmax -> d_out ----------------
__global__ void agg2_kernel(const float* __restrict__ H, const float* __restrict__ bias,
                            float* __restrict__ O, int N)
{
    int g = blockIdx.x * blockDim.x + threadIdx.x;
    int n = g >> 5, lane = g & 31;
    if (n >= N) return;
    const float2* __restrict__ H2 = reinterpret_cast<const float2*>(H);
    float edn = g_ed2[n];

    float w  = __expf(lrelu(g_es2[n] + edn));   // self-loop
    float ws = w;
    float2 hv = H2[n * 32 + lane];
    float accx = w * hv.x, accy = w * hv.y;

    int e = g_rowptr[n], e1 = g_rowptr[n + 1];
    for (; e + 8 <= e1; e += 8) {
        int s0 = g_csrc[e],     s1 = g_csrc[e + 1], s2 = g_csrc[e + 2], s3 = g_csrc[e + 3];
        int s4 = g_csrc[e + 4], s5 = g_csrc[e + 5], s6 = g_csrc[e + 6], s7 = g_csrc[e + 7];
        float a0 = g_es2[s0], a1 = g_es2[s1], a2 = g_es2[s2], a3 = g_es2[s3];
        float a4 = g_es2[s4], a5 = g_es2[s5], a6 = g_es2[s6], a7 = g_es2[s7];
        float2 h0 = H2[s0 * 32 + lane], h1v = H2[s1 * 32 + lane];
        float2 h2v = H2[s2 * 32 + lane], h3 = H2[s3 * 32 + lane];
        float2 h4 = H2[s4 * 32 + lane], h5 = H2[s5 * 32 + lane];
        float2 h6 = H2[s6 * 32 + lane], h7 = H2[s7 * 32 + lane];
        float x0 = __expf(lrelu(a0 + edn)), x1 = __expf(lrelu(a1 + edn));
        float x2 = __expf(lrelu(a2 + edn)), x3 = __expf(lrelu(a3 + edn));
        float x4 = __expf(lrelu(a4 + edn)), x5 = __expf(lrelu(a5 + edn));
        float x6 = __expf(lrelu(a6 + edn)), x7 = __expf(lrelu(a7 + edn));
        ws += ((x0 + x1) + (x2 + x3)) + ((x4 + x5) + (x6 + x7));
        accx = fmaf(x0, h0.x,  accx); accy = fmaf(x0, h0.y,  accy);
        accx = fmaf(x1, h1v.x, accx); accy = fmaf(x1, h1v.y, accy);
        accx = fmaf(x2, h2v.x, accx); accy = fmaf(x2, h2v.y, accy);
        accx = fmaf(x3, h3.x,  accx); accy = fmaf(x3, h3.y,  accy);
        accx = fmaf(x4, h4.x,  accx); accy = fmaf(x4, h4.y,  accy);
        accx = fmaf(x5, h5.x,  accx); accy = fmaf(x5, h5.y,  accy);
        accx = fmaf(x6, h6.x,  accx); accy = fmaf(x6, h6.y,  accy);
        accx = fmaf(x7, h7.x,  accx); accy = fmaf(x7, h7.y,  accy);
    }
    for (; e < e1; e++) {
        int s = g_csrc[e];
        float x = __expf(lrelu(g_es2[s] + edn));
        float2 hv2 = H2[s * 32 + lane];
        ws += x;
        accx = fmaf(x, hv2.x, accx);
        accy = fmaf(x, hv2.y, accy);
    }
    float2 bv = reinterpret_cast<const float2*>(bias)[lane];
    float vA = accx / ws + bv.x;
    float vB = accy / ws + bv.y;

    // log_softmax over 64 columns (2 per lane)
    float mx = fmaxf(vA, vB);
#pragma unroll
    for (int o = 16; o; o >>= 1) mx = fmaxf(mx, __shfl_xor_sync(0xffffffffu, mx, o));
    float se = __expf(vA - mx) + __expf(vB - mx);
#pragma unroll
    for (int o = 16; o; o >>= 1) se += __shfl_xor_sync(0xffffffffu, se, o);
    float lse = mx + logf(se);
    float2 ov; ov.x = vA - lse; ov.y = vB - lse;
    reinterpret_cast<float2*>(O)[n * 32 + lane] = ov;
}

// ---------------- launch ----------------
// Order: count(0) scanA(1) scanBC(2) scatter(3) gemm1(4) agg1(5) gemm2(6) agg2(7)
// -> ncu idx-3 capture lands on scatter (CSR-path sanity check).
extern "C" void kernel_launch(void* const* d_in, const int* in_sizes, int n_in,
                              void* d_out, int out_size)
{
    const float* x   = (const float*)d_in[0];
    const int*   ei  = (const int*)d_in[1];    // int32 OR int64 (probed per block)
    const float* W1  = (const float*)d_in[2];
    const float* as1 = (const float*)d_in[3];
    const float* ad1 = (const float*)d_in[4];
    const float* b1  = (const float*)d_in[5];
    const float* W2  = (const float*)d_in[6];
    const float* as2 = (const float*)d_in[7];
    const float* ad2 = (const float*)d_in[8];
    const float* b2  = (const float*)d_in[9];

    const int N = in_sizes[0] / 300;
    const int E = in_sizes[1] / 2;
    float* out = (float*)d_out;

    void *ph1, *ph1o, *ph2, *pes1, *ped1, *pes2, *ped2;
    cudaGetSymbolAddress(&ph1,  g_h1);
    cudaGetSymbolAddress(&ph1o, g_h1o);
    cudaGetSymbolAddress(&ph2,  g_h2);
    cudaGetSymbolAddress(&pes1, g_es1);
    cudaGetSymbolAddress(&ped1, g_ed1);
    cudaGetSymbolAddress(&pes2, g_es2);
    cudaGetSymbolAddress(&ped2, g_ed2);
    float* h1  = (float*)ph1;
    float* h1o = (float*)ph1o;
    float* h2  = (float*)ph2;

    const int tb = 256;
    const int G1 = (N + 31) / 32;
    const int SB = (N + 255) / 256;    // scan blocks (391)

    // CSR build (dst buckets), reused by both layers
    count_kernel  <<<(E + tb - 1) / tb, tb>>>(ei, E, N);
    scanA_kernel  <<<SB, 256>>>(N);
    scanBC_kernel <<<SB, 256>>>(N);
    scatter_kernel<<<(E + tb - 1) / tb, tb>>>(ei, E, N);

    // layer 1
    gemm_att_kernel<300, 8><<<G1, 128>>>(x, W1, h1, as1, ad1,
                                         (float*)pes1, (float*)ped1, N);
    agg1_kernel<<<(N + 7) / 8, tb>>>(h1, b1, h1o, N);

    // layer 2
    gemm_att_kernel<64, 1><<<G1, 128>>>(h1o, W2, h2, as2, ad2,
                                        (float*)pes2, (float*)ped2, N);
    agg2_kernel<<<(N + 7) / 8, tb>>>(h2, b2, out, N);
}

// round 15
// speedup vs baseline: 2.1585x; 1.3779x over previous
#include <cuda_runtime.h>

#define NMAX 100000
#define EMAX 1600000

// ---------------- scratch (device globals: no allocs allowed) ----------------
// g_deg is zero at module load; scanBC_kernel re-zeroes it after use each run.
__device__ float g_h1 [NMAX * 64];
__device__ float g_h1o[NMAX * 64];
__device__ float g_h2 [NMAX * 64];
__device__ float g_es1[NMAX * 8];
__device__ float g_ed1[NMAX * 8];
__device__ float g_es2[NMAX];
__device__ float g_ed2[NMAX];
__device__ int   g_deg[NMAX];
__device__ int   g_rowptr [NMAX + 1];
__device__ int   g_rowptr2[NMAX];      // bump cursors for scatter
__device__ int   g_csrc[EMAX];
__device__ int   g_blocksum[1024];

__device__ __forceinline__ float lrelu(float t) { return t > 0.f ? t : 0.2f * t; }

__device__ __forceinline__ unsigned f2tf32(float f) {
    unsigned u; asm("cvt.rna.tf32.f32 %0, %1;" : "=r"(u) : "f"(f)); return u;
}
__device__ __forceinline__ void mma_tf32(float* c, unsigned a0, unsigned a1,
                                         unsigned a2, unsigned a3,
                                         unsigned b0, unsigned b1) {
    asm volatile(
        "mma.sync.aligned.m16n8k8.row.col.f32.tf32.tf32.f32 "
        "{%0,%1,%2,%3}, {%4,%5,%6,%7}, {%8,%9}, {%0,%1,%2,%3};"
        : "+f"(c[0]), "+f"(c[1]), "+f"(c[2]), "+f"(c[3])
        : "r"(a0), "r"(a1), "r"(a2), "r"(a3), "r"(b0), "r"(b1));
}

// per-block edge-dtype probe: little-endian int64 ids (<2^31) have zero odd words
__device__ __forceinline__ int probe_is64_block(const int* __restrict__ ei, int* s_flag) {
    if (threadIdx.x == 0) {
        int all_zero = 1;
        for (int k = 1; k < 64; k += 2)
            if (ei[k] != 0) all_zero = 0;
        *s_flag = all_zero;
    }
    __syncthreads();
    return *s_flag;
}

// ---------------- CSR build ----------------
__global__ void count_kernel(const int* __restrict__ ei, int E, int N) {
    __shared__ int s_flag;
    int is64 = probe_is64_block(ei, &s_flag);
    int e = blockIdx.x * blockDim.x + threadIdx.x;
    if (e < E) {
        int dst = is64 ? ei[2 * (E + e)] : ei[E + e];
        if ((unsigned)dst < (unsigned)N) atomicAdd(&g_deg[dst], 1);
    }
}

// hierarchical scan, phase A: per-block degree sums (391 parallel blocks)
__global__ void scanA_kernel(int N) {
    __shared__ int red[256];
    int i = blockIdx.x * 256 + threadIdx.x;
    red[threadIdx.x] = (i < N) ? g_deg[i] : 0;
    __syncthreads();
    for (int off = 128; off; off >>= 1) {
        if (threadIdx.x < off) red[threadIdx.x] += red[threadIdx.x + off];
        __syncthreads();
    }
    if (threadIdx.x == 0) g_blocksum[blockIdx.x] = red[0];
}

// phase BC: block b sums blocksum[0..b), local exclusive scan, writes rowptr +
// bump cursors, re-zeroes g_deg for the next graph replay.
__global__ void scanBC_kernel(int N) {
    __shared__ int ps[256];
    int b = blockIdx.x, t = threadIdx.x;

    int part = 0;
    for (int j = t; j < b; j += 256) part += g_blocksum[j];
    ps[t] = part;
    __syncthreads();
    for (int off = 128; off; off >>= 1) {
        if (t < off) ps[t] += ps[t + off];
        __syncthreads();
    }
    int offset = ps[0];
    __syncthreads();

    int i = b * 256 + t;
    int d = (i < N) ? g_deg[i] : 0;
    ps[t] = d;
    __syncthreads();
    for (int off = 1; off < 256; off <<= 1) {
        int v = (t >= off) ? ps[t - off] : 0;
        __syncthreads();
        ps[t] += v;
        __syncthreads();
    }
    int ex = offset + ps[t] - d;
    if (i < N) {
        g_rowptr[i]  = ex;
        g_rowptr2[i] = ex;
        g_deg[i]     = 0;
    }
    if (i == N - 1) g_rowptr[N] = ex + d;
}

__global__ void scatter_kernel(const int* __restrict__ ei, int E, int N) {
    __shared__ int s_flag;
    int is64 = probe_is64_block(ei, &s_flag);
    int e = blockIdx.x * blockDim.x + threadIdx.x;
    if (e < E) {
        int dst, src;
        if (is64) { dst = ei[2 * (E + e)]; src = ei[2 * e]; }
        else      { dst = ei[E + e];       src = ei[e]; }
        if ((unsigned)dst >= (unsigned)N) return;
        int pos = atomicAdd(&g_rowptr2[dst], 1);
        if ((unsigned)pos < (unsigned)EMAX) g_csrc[pos] = src;
    }
}

// ---------------- tf32 tensor-core GEMM + fused attention logits ----------------
// Tile: 64 nodes x 64 cols, 256 threads (8 warps), warp = 16 rows x 32 cols.
// mma.sync.m16n8k8 tf32; operands staged in smem as tf32 (stride 36:
// fragment LDS banks = 4*gid + tig, conflict-free). Output tile stride 68.
template <int K, int HEADS>
__global__ __launch_bounds__(256)
void gemm_att_kernel(const float* __restrict__ X, const float* __restrict__ W,
                     float* __restrict__ H,
                     const float* __restrict__ as, const float* __restrict__ ad,
                     float* __restrict__ es, float* __restrict__ ed, int N)
{
    __shared__ __align__(16) unsigned sm_u[2 * 64 * 36];   // xs | ws (18.4 KB)
    unsigned* xs = sm_u;              // [64][36] tf32 X tile
    unsigned* ws = sm_u + 64 * 36;    // [64][36] tf32 W tile, [n][k]

    const int n0   = blockIdx.x * 64;
    const int w    = threadIdx.x >> 5;
    const int lane = threadIdx.x & 31;
    const int r0   = (w >> 1) * 16;       // warp row base
    const int cb0  = (w & 1) * 32;        // warp col base
    const int gid  = lane >> 2;
    const int tig  = lane & 3;

    float acc[4][4];
#pragma unroll
    for (int nt = 0; nt < 4; nt++)
#pragma unroll
        for (int q = 0; q < 4; q++) acc[nt][q] = 0.f;

    for (int k0 = 0; k0 < K; k0 += 32) {
        const int len = (K - k0 < 32) ? (K - k0) : 32;     // 32 or 12 (even)

        // stage X: 64 rows x 32 cols as float2 -> tf32
#pragma unroll
        for (int j = 0; j < 4; j++) {
            int idx = threadIdx.x + j * 256;               // 1024 float2 slots
            int r = idx >> 4, c2 = idx & 15;
            int n = n0 + r;
            float2 v = make_float2(0.f, 0.f);
            if (n < N && 2 * c2 < len)
                v = *reinterpret_cast<const float2*>(&X[(size_t)n * K + k0 + 2 * c2]);
            unsigned t0 = f2tf32(v.x), t1 = f2tf32(v.y);
            *reinterpret_cast<uint2*>(&xs[r * 36 + 2 * c2]) = make_uint2(t0, t1);
        }
        // stage W: [k][n] -> ws[n][k] tf32
#pragma unroll
        for (int j = 0; j < 8; j++) {
            int idx = threadIdx.x + j * 256;               // 2048
            int k = idx >> 6, c = idx & 63;
            float v = (k < len) ? W[(size_t)(k0 + k) * 64 + c] : 0.f;
            ws[c * 36 + k] = f2tf32(v);
        }
        __syncthreads();

#pragma unroll
        for (int k8 = 0; k8 < 32; k8 += 8) {
            unsigned a0 = xs[(r0 + gid) * 36 + k8 + tig];
            unsigned a1 = xs[(r0 + gid + 8) * 36 + k8 + tig];
            unsigned a2 = xs[(r0 + gid) * 36 + k8 + tig + 4];
            unsigned a3 = xs[(r0 + gid + 8) * 36 + k8 + tig + 4];
#pragma unroll
            for (int nt = 0; nt < 4; nt++) {
                int nn = cb0 + nt * 8 + gid;
                unsigned b0 = ws[nn * 36 + k8 + tig];
                unsigned b1 = ws[nn * 36 + k8 + tig + 4];
                mma_tf32(acc[nt], a0, a1, a2, a3, b0, b1);
            }
        }
        __syncthreads();
    }

    // C regs -> smem out tile (stride 68), then H + logits
    float* ot = reinterpret_cast<float*>(sm_u);            // 64*68 <= 2*64*36
#pragma unroll
    for (int nt = 0; nt < 4; nt++) {
        int c = cb0 + nt * 8 + 2 * tig;
        ot[(r0 + gid) * 68 + c]         = acc[nt][0];
        ot[(r0 + gid) * 68 + c + 1]     = acc[nt][1];
        ot[(r0 + gid + 8) * 68 + c]     = acc[nt][2];
        ot[(r0 + gid + 8) * 68 + c + 1] = acc[nt][3];
    }
    __syncthreads();

    // write H (coalesced float4)
#pragma unroll
    for (int j = 0; j < 4; j++) {
        int idx = threadIdx.x + j * 256;                   // 1024 float4
        int r = idx >> 4, c4 = (idx & 15) * 4;
        int n = n0 + r;
        if (n < N) {
            float4 v = *reinterpret_cast<float4*>(&ot[r * 68 + c4]);
            *reinterpret_cast<float4*>(&H[(size_t)n * 64 + c4]) = v;
        }
    }

    // attention logits from out tile
    if (HEADS == 8) {
        for (int p = threadIdx.x; p < 512; p += 256) {     // 64 rows x 8 heads
            int r = p >> 3, hh = p & 7;
            int n = n0 + r;
            if (n < N) {
                float s = 0.f, d = 0.f;
#pragma unroll
                for (int k = 0; k < 8; k++) {
                    float v = ot[r * 68 + hh * 8 + k];
                    s += v * as[hh * 8 + k];
                    d += v * ad[hh * 8 + k];
                }
                es[n * 8 + hh] = s;
                ed[n * 8 + hh] = d;
            }
        }
    } else {
        int r = threadIdx.x >> 2, part = threadIdx.x & 3;  // 64 rows x 4 parts
        float s = 0.f, d = 0.f;
#pragma unroll
        for (int k = 0; k < 16; k++) {
            float v = ot[r * 68 + part * 16 + k];
            s += v * as[part * 16 + k];
            d += v * ad[part * 16 + k];
        }
        s += __shfl_xor_sync(0xffffffffu, s, 1);
        s += __shfl_xor_sync(0xffffffffu, s, 2);
        d += __shfl_xor_sync(0xffffffffu, d, 1);
        d += __shfl_xor_sync(0xffffffffu, d, 2);
        int n = n0 + r;
        if (part == 0 && n < N) { es[n] = s; ed[n] = d; }
    }
}

// ---------------- layer-1 aggregation (float2 lanes, unroll x8) ----------------
__global__ void agg1_kernel(const float* __restrict__ H, const float* __restrict__ bias,
                            float* __restrict__ O, int N)
{
    int g = blockIdx.x * blockDim.x + threadIdx.x;
    int n = g >> 5, lane = g & 31;
    if (n >= N) return;
    const float2* __restrict__ H2 = reinterpret_cast<const float2*>(H);
    int hh = lane >> 2;
    float edv = g_ed1[n * 8 + hh];

    // self-loop (PyG default add_self_loops)
    float w = __expf(lrelu(g_es1[n * 8 + hh] + edv));
    float ws = w;
    float2 hv = H2[n * 32 + lane];
    float accx = w * hv.x, accy = w * hv.y;

    int e = g_rowptr[n], e1 = g_rowptr[n + 1];
    for (; e + 8 <= e1; e += 8) {
        int s0 = g_csrc[e],     s1 = g_csrc[e + 1], s2 = g_csrc[e + 2], s3 = g_csrc[e + 3];
        int s4 = g_csrc[e + 4], s5 = g_csrc[e + 5], s6 = g_csrc[e + 6], s7 = g_csrc[e + 7];
        float a0 = g_es1[s0 * 8 + hh], a1 = g_es1[s1 * 8 + hh];
        float a2 = g_es1[s2 * 8 + hh], a3 = g_es1[s3 * 8 + hh];
        float a4 = g_es1[s4 * 8 + hh], a5 = g_es1[s5 * 8 + hh];
        float a6 = g_es1[s6 * 8 + hh], a7 = g_es1[s7 * 8 + hh];
        float2 h0 = H2[s0 * 32 + lane], h1v = H2[s1 * 32 + lane];
        float2 h2v = H2[s2 * 32 + lane], h3 = H2[s3 * 32 + lane];
        float2 h4 = H2[s4 * 32 + lane], h5 = H2[s5 * 32 + lane];
        float2 h6 = H2[s6 * 32 + lane], h7 = H2[s7 * 32 + lane];
        float x0 = __expf(lrelu(a0 + edv)), x1 = __expf(lrelu(a1 + edv));
        float x2 = __expf(lrelu(a2 + edv)), x3 = __expf(lrelu(a3 + edv));
        float x4 = __expf(lrelu(a4 + edv)), x5 = __expf(lrelu(a5 + edv));
        float x6 = __expf(lrelu(a6 + edv)), x7 = __expf(lrelu(a7 + edv));
        ws += ((x0 + x1) + (x2 + x3)) + ((x4 + x5) + (x6 + x7));
        accx = fmaf(x0, h0.x,  accx); accy = fmaf(x0, h0.y,  accy);
        accx = fmaf(x1, h1v.x, accx); accy = fmaf(x1, h1v.y, accy);
        accx = fmaf(x2, h2v.x, accx); accy = fmaf(x2, h2v.y, accy);
        accx = fmaf(x3, h3.x,  accx); accy = fmaf(x3, h3.y,  accy);
        accx = fmaf(x4, h4.x,  accx); accy = fmaf(x4, h4.y,  accy);
        accx = fmaf(x5, h5.x,  accx); accy = fmaf(x5, h5.y,  accy);
        accx = fmaf(x6, h6.x,  accx); accy = fmaf(x6, h6.y,  accy);
        accx = fmaf(x7, h7.x,  accx); accy = fmaf(x7, h7.y,  accy);
    }
    for (; e < e1; e++) {
        int s = g_csrc[e];
        float x = __expf(lrelu(g_es1[s * 8 + hh] + edv));
        float2 hv2 = H2[s * 32 + lane];
        ws += x;
        accx = fmaf(x, hv2.x, accx);
        accy = fmaf(x, hv2.y, accy);
    }
    float2 bv = reinterpret_cast<const float2*>(bias)[lane];
    float ox = accx / ws + bv.x;
    float oy = accy / ws + bv.y;
    float2 ov;
    ov.x = ox > 0.f ? ox : (__expf(ox) - 1.f);   // ELU
    ov.y = oy > 0.f ? oy : (__expf(oy) - 1.f);
    reinterpret_cast<float2*>(O)[n * 32 + lane] = ov;
}

// ---------------- layer-2 aggregation + bias + log_softmax -> d_out ----------------
__global__ void agg2_kernel(const float* __restrict__ H, const float* __restrict__ bias,
                            float* __restrict__ O, int N)
{
    int g = blockIdx.x * blockDim.x + threadIdx.x;
    int n = g >> 5, lane = g & 31;
    if (n >= N) return;
    const float2* __restrict__ H2 = reinterpret_cast<const float2*>(H);
    float edn = g_ed2[n];

    float w  = __expf(lrelu(g_es2[n] + edn));   // self-loop
    float ws = w;
    float2 hv = H2[n * 32 + lane];
    float accx = w * hv.x, accy = w * hv.y;

    int e = g_rowptr[n], e1 = g_rowptr[n + 1];
    for (; e + 8 <= e1; e += 8) {
        int s0 = g_csrc[e],     s1 = g_csrc[e + 1], s2 = g_csrc[e + 2], s3 = g_csrc[e + 3];
        int s4 = g_csrc[e + 4], s5 = g_csrc[e + 5], s6 = g_csrc[e + 6], s7 = g_csrc[e + 7];
        float a0 = g_es2[s0], a1 = g_es2[s1], a2 = g_es2[s2], a3 = g_es2[s3];
        float a4 = g_es2[s4], a5 = g_es2[s5], a6 = g_es2[s6], a7 = g_es2[s7];
        float2 h0 = H2[s0 * 32 + lane], h1v = H2[s1 * 32 + lane];
        float2 h2v = H2[s2 * 32 + lane], h3 = H2[s3 * 32 + lane];
        float2 h4 = H2[s4 * 32 + lane], h5 = H2[s5 * 32 + lane];
        float2 h6 = H2[s6 * 32 + lane], h7 = H2[s7 * 32 + lane];
        float x0 = __expf(lrelu(a0 + edn)), x1 = __expf(lrelu(a1 + edn));
        float x2 = __expf(lrelu(a2 + edn)), x3 = __expf(lrelu(a3 + edn));
        float x4 = __expf(lrelu(a4 + edn)), x5 = __expf(lrelu(a5 + edn));
        float x6 = __expf(lrelu(a6 + edn)), x7 = __expf(lrelu(a7 + edn));
        ws += ((x0 + x1) + (x2 + x3)) + ((x4 + x5) + (x6 + x7));
        accx = fmaf(x0, h0.x,  accx); accy = fmaf(x0, h0.y,  accy);
        accx = fmaf(x1, h1v.x, accx); accy = fmaf(x1, h1v.y, accy);
        accx = fmaf(x2, h2v.x, accx); accy = fmaf(x2, h2v.y, accy);
        accx = fmaf(x3, h3.x,  accx); accy = fmaf(x3, h3.y,  accy);
        accx = fmaf(x4, h4.x,  accx); accy = fmaf(x4, h4.y,  accy);
        accx = fmaf(x5, h5.x,  accx); accy = fmaf(x5, h5.y,  accy);
        accx = fmaf(x6, h6.x,  accx); accy = fmaf(x6, h6.y,  accy);
        accx = fmaf(x7, h7.x,  accx); accy = fmaf(x7, h7.y,  accy);
    }
    for (; e < e1; e++) {
        int s = g_csrc[e];
        float x = __expf(lrelu(g_es2[s] + edn));
        float2 hv2 = H2[s * 32 + lane];
        ws += x;
        accx = fmaf(x, hv2.x, accx);
        accy = fmaf(x, hv2.y, accy);
    }
    float2 bv = reinterpret_cast<const float2*>(bias)[lane];
    float vA = accx / ws + bv.x;
    float vB = accy / ws + bv.y;

    // log_softmax over 64 columns (2 per lane)
    float mx = fmaxf(vA, vB);
#pragma unroll
    for (int o = 16; o; o >>= 1) mx = fmaxf(mx, __shfl_xor_sync(0xffffffffu, mx, o));
    float se = __expf(vA - mx) + __expf(vB - mx);
#pragma unroll
    for (int o = 16; o; o >>= 1) se += __shfl_xor_sync(0xffffffffu, se, o);
    float lse = mx + logf(se);
    float2 ov; ov.x = vA - lse; ov.y = vB - lse;
    reinterpret_cast<float2*>(O)[n * 32 + lane] = ov;
}

// ---------------- launch ----------------
// Order: count(0) scanA(1) scanBC(2) gemm1(3) scatter(4) agg1(5) gemm2(6) agg2(7)
// -> ncu idx-3 capture lands on the NEW tf32 gemm1.
extern "C" void kernel_launch(void* const* d_in, const int* in_sizes, int n_in,
                              void* d_out, int out_size)
{
    const float* x   = (const float*)d_in[0];
    const int*   ei  = (const int*)d_in[1];    // int32 OR int64 (probed per block)
    const float* W1  = (const float*)d_in[2];
    const float* as1 = (const float*)d_in[3];
    const float* ad1 = (const float*)d_in[4];
    const float* b1  = (const float*)d_in[5];
    const float* W2  = (const float*)d_in[6];
    const float* as2 = (const float*)d_in[7];
    const float* ad2 = (const float*)d_in[8];
    const float* b2  = (const float*)d_in[9];

    const int N = in_sizes[0] / 300;
    const int E = in_sizes[1] / 2;
    float* out = (float*)d_out;

    void *ph1, *ph1o, *ph2, *pes1, *ped1, *pes2, *ped2;
    cudaGetSymbolAddress(&ph1,  g_h1);
    cudaGetSymbolAddress(&ph1o, g_h1o);
    cudaGetSymbolAddress(&ph2,  g_h2);
    cudaGetSymbolAddress(&pes1, g_es1);
    cudaGetSymbolAddress(&ped1, g_ed1);
    cudaGetSymbolAddress(&pes2, g_es2);
    cudaGetSymbolAddress(&ped2, g_ed2);
    float* h1  = (float*)ph1;
    float* h1o = (float*)ph1o;
    float* h2  = (float*)ph2;

    const int tb = 256;
    const int G  = (N + 63) / 64;      // 64-node gemm tiles
    const int SB = (N + 255) / 256;    // scan blocks

    // CSR build (dst buckets), reused by both layers
    count_kernel  <<<(E + tb - 1) / tb, tb>>>(ei, E, N);
    scanA_kernel  <<<SB, 256>>>(N);
    scanBC_kernel <<<SB, 256>>>(N);

    // layer-1 GEMM (independent of CSR; placed at capture slot 3)
    gemm_att_kernel<300, 8><<<G, 256>>>(x, W1, h1, as1, ad1,
                                        (float*)pes1, (float*)ped1, N);
    scatter_kernel<<<(E + tb - 1) / tb, tb>>>(ei, E, N);

    agg1_kernel<<<(N + 7) / 8, tb>>>(h1, b1, h1o, N);

    // layer 2
    gemm_att_kernel<64, 1><<<G, 256>>>(h1o, W2, h2, as2, ad2,
                                       (float*)pes2, (float*)ped2, N);
    agg2_kernel<<<(N + 7) / 8, tb>>>(h2, b2, out, N);
}

// round 16
// speedup vs baseline: 2.5314x; 1.1728x over previous
#include <cuda_runtime.h>

#define NMAX 100000
#define EMAX 1600000

// ---------------- scratch (device globals: no allocs allowed) ----------------
// g_deg is zero at module load; scanBC_kernel re-zeroes it after use each run.
__device__ float g_h1 [NMAX * 64];
__device__ float g_h1o[NMAX * 64];
__device__ float g_h2 [NMAX * 64];
__device__ float g_es1[NMAX * 8];
__device__ float g_ed1[NMAX * 8];
__device__ float g_es2[NMAX];
__device__ float g_ed2[NMAX];
__device__ int   g_deg[NMAX];
__device__ int   g_rowptr [NMAX + 1];
__device__ int   g_rowptr2[NMAX];      // bump cursors for scatter
__device__ int   g_csrc[EMAX];
__device__ int   g_blocksum[1024];
__device__ int   g_is64;
__device__ float g_wt1[64 * 300];      // W1 transposed [n][k]
__device__ float g_wt2[64 * 64];       // W2 transposed [n][k]

__device__ __forceinline__ float lrelu(float t) { return t > 0.f ? t : 0.2f * t; }

__device__ __forceinline__ void mma_tf32(float* c, unsigned a0, unsigned a1,
                                         unsigned a2, unsigned a3,
                                         unsigned b0, unsigned b1) {
    asm volatile(
        "mma.sync.aligned.m16n8k8.row.col.f32.tf32.tf32.f32 "
        "{%0,%1,%2,%3}, {%4,%5,%6,%7}, {%8,%9}, {%0,%1,%2,%3};"
        : "+f"(c[0]), "+f"(c[1]), "+f"(c[2]), "+f"(c[3])
        : "r"(a0), "r"(a1), "r"(a2), "r"(a3), "r"(b0), "r"(b1));
}

__device__ __forceinline__ void cp16(void* smem, const void* gmem) {
    unsigned saddr = (unsigned)__cvta_generic_to_shared(smem);
    asm volatile("cp.async.cg.shared.global [%0], [%1], 16;"
                 :: "r"(saddr), "l"(gmem));
}

// ---------------- edge dtype probe (one tiny launch) ----------------
// little-endian int64 node ids (<2^31) have zero odd 32-bit words
__global__ void probe_kernel(const int* __restrict__ ei) {
    if (threadIdx.x == 0) {
        int all_zero = 1;
        for (int k = 1; k < 64; k += 2)
            if (ei[k] != 0) all_zero = 0;
        g_is64 = all_zero;
    }
}

// ---------------- W transpose: Wt[n][k] = W[k][n] ----------------
__global__ void transposeW_kernel(const float* __restrict__ W, float* __restrict__ Wt, int K) {
    int i = blockIdx.x * blockDim.x + threadIdx.x;
    if (i < K * 64) {
        int k = i >> 6, n = i & 63;
        Wt[n * K + k] = W[i];
    }
}

// ---------------- hierarchical scan ----------------
__global__ void scanA_kernel(int N) {
    __shared__ int red[256];
    int i = blockIdx.x * 256 + threadIdx.x;
    red[threadIdx.x] = (i < N) ? g_deg[i] : 0;
    __syncthreads();
    for (int off = 128; off; off >>= 1) {
        if (threadIdx.x < off) red[threadIdx.x] += red[threadIdx.x + off];
        __syncthreads();
    }
    if (threadIdx.x == 0) g_blocksum[blockIdx.x] = red[0];
}

__global__ void scanBC_kernel(int N) {
    __shared__ int ps[256];
    int b = blockIdx.x, t = threadIdx.x;

    int part = 0;
    for (int j = t; j < b; j += 256) part += g_blocksum[j];
    ps[t] = part;
    __syncthreads();
    for (int off = 128; off; off >>= 1) {
        if (t < off) ps[t] += ps[t + off];
        __syncthreads();
    }
    int offset = ps[0];
    __syncthreads();

    int i = b * 256 + t;
    int d = (i < N) ? g_deg[i] : 0;
    ps[t] = d;
    __syncthreads();
    for (int off = 1; off < 256; off <<= 1) {
        int v = (t >= off) ? ps[t - off] : 0;
        __syncthreads();
        ps[t] += v;
        __syncthreads();
    }
    int ex = offset + ps[t] - d;
    if (i < N) {
        g_rowptr[i]  = ex;
        g_rowptr2[i] = ex;
        g_deg[i]     = 0;
    }
    if (i == N - 1) g_rowptr[N] = ex + d;
}

__global__ void scatter_kernel(const int* __restrict__ ei, int E, int N) {
    int e = blockIdx.x * blockDim.x + threadIdx.x;
    if (e < E) {
        int dst, src;
        if (g_is64) { dst = ei[2 * (E + e)]; src = ei[2 * e]; }
        else        { dst = ei[E + e];       src = ei[e]; }
        if ((unsigned)dst >= (unsigned)N) return;
        int pos = atomicAdd(&g_rowptr2[dst], 1);
        if ((unsigned)pos < (unsigned)EMAX) g_csrc[pos] = src;
    }
}

// ---------------- tf32 tensor GEMM + attention logits (+optional count rider) ----------------
// Tile: 64 nodes x 64 cols, 256 threads (8 warps), warp = 16 rows x 32 cols.
// Operands cp.async'd directly into smem as raw fp32 (mma.tf32 truncates).
// Stride 68 floats: 16B-aligned rows AND conflict-free fragment LDS (4*gid+tig).
template <int K, int HEADS, bool DO_COUNT>
__global__ __launch_bounds__(256)
void gemm_att_kernel(const float* __restrict__ X, const float* __restrict__ Wt,
                     float* __restrict__ H,
                     const float* __restrict__ as, const float* __restrict__ ad,
                     float* __restrict__ es, float* __restrict__ ed, int N,
                     const int* __restrict__ ei, int E, int gemmBlocks)
{
    if (DO_COUNT && (int)blockIdx.x >= gemmBlocks) {
        int base   = ((int)blockIdx.x - gemmBlocks) * 256 + threadIdx.x;
        int stride = ((int)gridDim.x - gemmBlocks) * 256;
        if (g_is64) {
            for (int e = base; e < E; e += stride) {
                int dst = ei[2 * (E + e)];
                if ((unsigned)dst < (unsigned)N) atomicAdd(&g_deg[dst], 1);
            }
        } else {
            for (int e = base; e < E; e += stride) {
                int dst = ei[E + e];
                if ((unsigned)dst < (unsigned)N) atomicAdd(&g_deg[dst], 1);
            }
        }
        return;
    }

    __shared__ __align__(16) float xs[64 * 68];
    __shared__ __align__(16) float ws[64 * 68];

    const int n0   = blockIdx.x * 64;
    const int w    = threadIdx.x >> 5;
    const int lane = threadIdx.x & 31;
    const int r0   = (w >> 1) * 16;       // warp row base
    const int cb0  = (w & 1) * 32;        // warp col base
    const int gid  = lane >> 2;
    const int tig  = lane & 3;

    float acc[4][4];
#pragma unroll
    for (int nt = 0; nt < 4; nt++)
#pragma unroll
        for (int q = 0; q < 4; q++) acc[nt][q] = 0.f;

    for (int k0 = 0; k0 < K; k0 += 64) {
        const int len  = (K - k0 < 64) ? (K - k0) : 64;   // 64 or 44
        const int nseg = (len + 3) >> 2;                  // 16 or 11

        // stage X and Wt via cp.async (2048 16B segments; zeros for pad/OOB)
#pragma unroll
        for (int j = 0; j < 8; j++) {
            int idx = threadIdx.x + j * 256;              // 0..2047
            int r   = (idx >> 4) & 63;
            int s   = idx & 15;
            bool isW = idx >= 1024;
            float* dstp = (isW ? ws : xs) + r * 68 + 4 * s;
            if (s < nseg) {
                if (isW) {
                    cp16(dstp, Wt + (size_t)r * K + k0 + 4 * s);
                } else {
                    int n = n0 + r;
                    if (n < N) cp16(dstp, X + (size_t)n * K + k0 + 4 * s);
                    else *reinterpret_cast<float4*>(dstp) = make_float4(0.f, 0.f, 0.f, 0.f);
                }
            } else {
                *reinterpret_cast<float4*>(dstp) = make_float4(0.f, 0.f, 0.f, 0.f);
            }
        }
        asm volatile("cp.async.commit_group;" ::: "memory");
        asm volatile("cp.async.wait_group 0;" ::: "memory");
        __syncthreads();

#pragma unroll
        for (int k8 = 0; k8 < 64; k8 += 8) {
            unsigned a0 = __float_as_uint(xs[(r0 + gid) * 68 + k8 + tig]);
            unsigned a1 = __float_as_uint(xs[(r0 + gid + 8) * 68 + k8 + tig]);
            unsigned a2 = __float_as_uint(xs[(r0 + gid) * 68 + k8 + tig + 4]);
            unsigned a3 = __float_as_uint(xs[(r0 + gid + 8) * 68 + k8 + tig + 4]);
#pragma unroll
            for (int nt = 0; nt < 4; nt++) {
                int nn = cb0 + nt * 8 + gid;
                unsigned b0 = __float_as_uint(ws[nn * 68 + k8 + tig]);
                unsigned b1 = __float_as_uint(ws[nn * 68 + k8 + tig + 4]);
                mma_tf32(acc[nt], a0, a1, a2, a3, b0, b1);
            }
        }
        __syncthreads();
    }

    // C regs -> out tile in xs (stride 68), then H + logits
    float* ot = xs;
#pragma unroll
    for (int nt = 0; nt < 4; nt++) {
        int c = cb0 + nt * 8 + 2 * tig;
        ot[(r0 + gid) * 68 + c]         = acc[nt][0];
        ot[(r0 + gid) * 68 + c + 1]     = acc[nt][1];
        ot[(r0 + gid + 8) * 68 + c]     = acc[nt][2];
        ot[(r0 + gid + 8) * 68 + c + 1] = acc[nt][3];
    }
    __syncthreads();

    // write H (coalesced float4)
#pragma unroll
    for (int j = 0; j < 4; j++) {
        int idx = threadIdx.x + j * 256;                  // 1024 float4
        int r = idx >> 4, c4 = (idx & 15) * 4;
        int n = n0 + r;
        if (n < N) {
            float4 v = *reinterpret_cast<float4*>(&ot[r * 68 + c4]);
            *reinterpret_cast<float4*>(&H[(size_t)n * 64 + c4]) = v;
        }
    }

    // attention logits from out tile
    if (HEADS == 8) {
        for (int p = threadIdx.x; p < 512; p += 256) {    // 64 rows x 8 heads
            int r = p >> 3, hh = p & 7;
            int n = n0 + r;
            if (n < N) {
                float s = 0.f, d = 0.f;
#pragma unroll
                for (int k = 0; k < 8; k++) {
                    float v = ot[r * 68 + hh * 8 + k];
                    s += v * as[hh * 8 + k];
                    d += v * ad[hh * 8 + k];
                }
                es[n * 8 + hh] = s;
                ed[n * 8 + hh] = d;
            }
        }
    } else {
        int r = threadIdx.x >> 2, part = threadIdx.x & 3; // 64 rows x 4 parts
        float s = 0.f, d = 0.f;
#pragma unroll
        for (int k = 0; k < 16; k++) {
            float v = ot[r * 68 + part * 16 + k];
            s += v * as[part * 16 + k];
            d += v * ad[part * 16 + k];
        }
        s += __shfl_xor_sync(0xffffffffu, s, 1);
        s += __shfl_xor_sync(0xffffffffu, s, 2);
        d += __shfl_xor_sync(0xffffffffu, d, 1);
        d += __shfl_xor_sync(0xffffffffu, d, 2);
        int n = n0 + r;
        if (part == 0 && n < N) { es[n] = s; ed[n] = d; }
    }
}

// ---------------- layer-1 aggregation (float2 lanes, unroll x8) ----------------
__global__ void agg1_kernel(const float* __restrict__ H, const float* __restrict__ bias,
                            float* __restrict__ O, int N)
{
    int g = blockIdx.x * blockDim.x + threadIdx.x;
    int n = g >> 5, lane = g & 31;
    if (n >= N) return;
    const float2* __restrict__ H2 = reinterpret_cast<const float2*>(H);
    int hh = lane >> 2;
    float edv = g_ed1[n * 8 + hh];

    // self-loop (PyG default add_self_loops)
    float w = __expf(lrelu(g_es1[n * 8 + hh] + edv));
    float ws = w;
    float2 hv = H2[n * 32 + lane];
    float accx = w * hv.x, accy = w * hv.y;

    int e = g_rowptr[n], e1 = g_rowptr[n + 1];
    for (; e + 8 <= e1; e += 8) {
        int s0 = g_csrc[e],     s1 = g_csrc[e + 1], s2 = g_csrc[e + 2], s3 = g_csrc[e + 3];
        int s4 = g_csrc[e + 4], s5 = g_csrc[e + 5], s6 = g_csrc[e + 6], s7 = g_csrc[e + 7];
        float a0 = g_es1[s0 * 8 + hh], a1 = g_es1[s1 * 8 + hh];
        float a2 = g_es1[s2 * 8 + hh], a3 = g_es1[s3 * 8 + hh];
        float a4 = g_es1[s4 * 8 + hh], a5 = g_es1[s5 * 8 + hh];
        float a6 = g_es1[s6 * 8 + hh], a7 = g_es1[s7 * 8 + hh];
        float2 h0 = H2[s0 * 32 + lane], h1v = H2[s1 * 32 + lane];
        float2 h2v = H2[s2 * 32 + lane], h3 = H2[s3 * 32 + lane];
        float2 h4 = H2[s4 * 32 + lane], h5 = H2[s5 * 32 + lane];
        float2 h6 = H2[s6 * 32 + lane], h7 = H2[s7 * 32 + lane];
        float x0 = __expf(lrelu(a0 + edv)), x1 = __expf(lrelu(a1 + edv));
        float x2 = __expf(lrelu(a2 + edv)), x3 = __expf(lrelu(a3 + edv));
        float x4 = __expf(lrelu(a4 + edv)), x5 = __expf(lrelu(a5 + edv));
        float x6 = __expf(lrelu(a6 + edv)), x7 = __expf(lrelu(a7 + edv));
        ws += ((x0 + x1) + (x2 + x3)) + ((x4 + x5) + (x6 + x7));
        accx = fmaf(x0, h0.x,  accx); accy = fmaf(x0, h0.y,  accy);
        accx = fmaf(x1, h1v.x, accx); accy = fmaf(x1, h1v.y, accy);
        accx = fmaf(x2, h2v.x, accx); accy = fmaf(x2, h2v.y, accy);
        accx = fmaf(x3, h3.x,  accx); accy = fmaf(x3, h3.y,  accy);
        accx = fmaf(x4, h4.x,  accx); accy = fmaf(x4, h4.y,  accy);
        accx = fmaf(x5, h5.x,  accx); accy = fmaf(x5, h5.y,  accy);
        accx = fmaf(x6, h6.x,  accx); accy = fmaf(x6, h6.y,  accy);
        accx = fmaf(x7, h7.x,  accx); accy = fmaf(x7, h7.y,  accy);
    }
    for (; e < e1; e++) {
        int s = g_csrc[e];
        float x = __expf(lrelu(g_es1[s * 8 + hh] + edv));
        float2 hv2 = H2[s * 32 + lane];
        ws += x;
        accx = fmaf(x, hv2.x, accx);
        accy = fmaf(x, hv2.y, accy);
    }
    float2 bv = reinterpret_cast<const float2*>(bias)[lane];
    float ox = accx / ws + bv.x;
    float oy = accy / ws + bv.y;
    float2 ov;
    ov.x = ox > 0.f ? ox : (__expf(ox) - 1.f);   // ELU
    ov.y = oy > 0.f ? oy : (__expf(oy) - 1.f);
    reinterpret_cast<float2*>(O)[n * 32 + lane] = ov;
}

// ---------------- layer-2 aggregation + bias + log_softmax -> d_out ----------------
__global__ void agg2_kernel(const float* __restrict__ H, const float* __restrict__ bias,
                            float* __restrict__ O, int N)
{
    int g = blockIdx.x * blockDim.x + threadIdx.x;
    int n = g >> 5, lane = g & 31;
    if (n >= N) return;
    const float2* __restrict__ H2 = reinterpret_cast<const float2*>(H);
    float edn = g_ed2[n];

    float w  = __expf(lrelu(g_es2[n] + edn));   // self-loop
    float ws = w;
    float2 hv = H2[n * 32 + lane];
    float accx = w * hv.x, accy = w * hv.y;

    int e = g_rowptr[n], e1 = g_rowptr[n + 1];
    for (; e + 8 <= e1; e += 8) {
        int s0 = g_csrc[e],     s1 = g_csrc[e + 1], s2 = g_csrc[e + 2], s3 = g_csrc[e + 3];
        int s4 = g_csrc[e + 4], s5 = g_csrc[e + 5], s6 = g_csrc[e + 6], s7 = g_csrc[e + 7];
        float a0 = g_es2[s0], a1 = g_es2[s1], a2 = g_es2[s2], a3 = g_es2[s3];
        float a4 = g_es2[s4], a5 = g_es2[s5], a6 = g_es2[s6], a7 = g_es2[s7];
        float2 h0 = H2[s0 * 32 + lane], h1v = H2[s1 * 32 + lane];
        float2 h2v = H2[s2 * 32 + lane], h3 = H2[s3 * 32 + lane];
        float2 h4 = H2[s4 * 32 + lane], h5 = H2[s5 * 32 + lane];
        float2 h6 = H2[s6 * 32 + lane], h7 = H2[s7 * 32 + lane];
        float x0 = __expf(lrelu(a0 + edn)), x1 = __expf(lrelu(a1 + edn));
        float x2 = __expf(lrelu(a2 + edn)), x3 = __expf(lrelu(a3 + edn));
        float x4 = __expf(lrelu(a4 + edn)), x5 = __expf(lrelu(a5 + edn));
        float x6 = __expf(lrelu(a6 + edn)), x7 = __expf(lrelu(a7 + edn));
        ws += ((x0 + x1) + (x2 + x3)) + ((x4 + x5) + (x6 + x7));
        accx = fmaf(x0, h0.x,  accx); accy = fmaf(x0, h0.y,  accy);
        accx = fmaf(x1, h1v.x, accx); accy = fmaf(x1, h1v.y, accy);
        accx = fmaf(x2, h2v.x, accx); accy = fmaf(x2, h2v.y, accy);
        accx = fmaf(x3, h3.x,  accx); accy = fmaf(x3, h3.y,  accy);
        accx = fmaf(x4, h4.x,  accx); accy = fmaf(x4, h4.y,  accy);
        accx = fmaf(x5, h5.x,  accx); accy = fmaf(x5, h5.y,  accy);
        accx = fmaf(x6, h6.x,  accx); accy = fmaf(x6, h6.y,  accy);
        accx = fmaf(x7, h7.x,  accx); accy = fmaf(x7, h7.y,  accy);
    }
    for (; e < e1; e++) {
        int s = g_csrc[e];
        float x = __expf(lrelu(g_es2[s] + edn));
        float2 hv2 = H2[s * 32 + lane];
        ws += x;
        accx = fmaf(x, hv2.x, accx);
        accy = fmaf(x, hv2.y, accy);
    }
    float2 bv = reinterpret_cast<const float2*>(bias)[lane];
    float vA = accx / ws + bv.x;
    float vB = accy / ws + bv.y;

    // log_softmax over 64 columns (2 per lane)
    float mx = fmaxf(vA, vB);
#pragma unroll
    for (int o = 16; o; o >>= 1) mx = fmaxf(mx, __shfl_xor_sync(0xffffffffu, mx, o));
    float se = __expf(vA - mx) + __expf(vB - mx);
#pragma unroll
    for (int o = 16; o; o >>= 1) se += __shfl_xor_sync(0xffffffffu, se, o);
    float lse = mx + logf(se);
    float2 ov; ov.x = vA - lse; ov.y = vB - lse;
    reinterpret_cast<float2*>(O)[n * 32 + lane] = ov;
}

// ---------------- launch ----------------
// Order: probe(0) tW1(1) tW2(2) gemm1+count(3) scanA(4) scanBC(5) scatter(6)
//        agg1(7) gemm2(8) agg2(9)  -> ncu idx-3 capture = new gemm1.
extern "C" void kernel_launch(void* const* d_in, const int* in_sizes, int n_in,
                              void* d_out, int out_size)
{
    const float* x   = (const float*)d_in[0];
    const int*   ei  = (const int*)d_in[1];    // int32 OR int64 (probed)
    const float* W1  = (const float*)d_in[2];
    const float* as1 = (const float*)d_in[3];
    const float* ad1 = (const float*)d_in[4];
    const float* b1  = (const float*)d_in[5];
    const float* W2  = (const float*)d_in[6];
    const float* as2 = (const float*)d_in[7];
    const float* ad2 = (const float*)d_in[8];
    const float* b2  = (const float*)d_in[9];

    const int N = in_sizes[0] / 300;
    const int E = in_sizes[1] / 2;
    float* out = (float*)d_out;

    void *ph1, *ph1o, *ph2, *pes1, *ped1, *pes2, *ped2, *pwt1, *pwt2;
    cudaGetSymbolAddress(&ph1,  g_h1);
    cudaGetSymbolAddress(&ph1o, g_h1o);
    cudaGetSymbolAddress(&ph2,  g_h2);
    cudaGetSymbolAddress(&pes1, g_es1);
    cudaGetSymbolAddress(&ped1, g_ed1);
    cudaGetSymbolAddress(&pes2, g_es2);
    cudaGetSymbolAddress(&ped2, g_ed2);
    cudaGetSymbolAddress(&pwt1, g_wt1);
    cudaGetSymbolAddress(&pwt2, g_wt2);
    float* h1  = (float*)ph1;
    float* h1o = (float*)ph1o;
    float* h2  = (float*)ph2;
    float* wt1 = (float*)pwt1;
    float* wt2 = (float*)pwt2;

    const int tb = 256;
    const int G  = (N + 63) / 64;      // 64-node gemm tiles
    const int SB = (N + 255) / 256;    // scan blocks
    const int CB = 512;                // count rider blocks

    probe_kernel     <<<1, 32>>>(ei);
    transposeW_kernel<<<(300 * 64 + tb - 1) / tb, tb>>>(W1, wt1, 300);
    transposeW_kernel<<<(64 * 64 + tb - 1) / tb, tb>>>(W2, wt2, 64);

    // layer-1 GEMM with degree-count rider (independent halves)
    gemm_att_kernel<300, 8, true><<<G + CB, 256>>>(x, wt1, h1, as1, ad1,
                                                   (float*)pes1, (float*)ped1, N,
                                                   ei, E, G);
    scanA_kernel  <<<SB, 256>>>(N);
    scanBC_kernel <<<SB, 256>>>(N);
    scatter_kernel<<<(E + tb - 1) / tb, tb>>>(ei, E, N);

    agg1_kernel<<<(N + 7) / 8, tb>>>(h1, b1, h1o, N);

    // layer 2
    gemm_att_kernel<64, 1, false><<<G, 256>>>(h1o, wt2, h2, as2, ad2,
                                              (float*)pes2, (float*)ped2, N,
                                              ei, E, G);
    agg2_kernel<<<(N + 7) / 8, tb>>>(h2, b2, out, N);
}

// round 17
// speedup vs baseline: 2.5886x; 1.0226x over previous
#include <cuda_runtime.h>

#define NMAX 100000
#define EMAX 1600000

// ---------------- scratch (device globals: no allocs allowed) ----------------
// g_deg is zero at module load; scanBC_kernel re-zeroes it after use each run.
__device__ float g_h1 [NMAX * 64];
__device__ float g_h1o[NMAX * 64];
__device__ float g_h2 [NMAX * 64];
__device__ float g_es1[NMAX * 8];
__device__ float g_ed1[NMAX * 8];
__device__ float g_es2[NMAX];
__device__ float g_ed2[NMAX];
__device__ int   g_deg[NMAX];
__device__ int   g_rowptr [NMAX + 1];
__device__ int   g_rowptr2[NMAX];      // bump cursors for scatter
__device__ int   g_csrc[EMAX];
__device__ int   g_blocksum[1024];
__device__ int   g_is64;
__device__ float g_wt1[64 * 300];      // W1 transposed [n][k]
__device__ float g_wt2[64 * 64];       // W2 transposed [n][k]

__device__ __forceinline__ float lrelu(float t) { return t > 0.f ? t : 0.2f * t; }

__device__ __forceinline__ void mma_tf32(float* c, unsigned a0, unsigned a1,
                                         unsigned a2, unsigned a3,
                                         unsigned b0, unsigned b1) {
    asm volatile(
        "mma.sync.aligned.m16n8k8.row.col.f32.tf32.tf32.f32 "
        "{%0,%1,%2,%3}, {%4,%5,%6,%7}, {%8,%9}, {%0,%1,%2,%3};"
        : "+f"(c[0]), "+f"(c[1]), "+f"(c[2]), "+f"(c[3])
        : "r"(a0), "r"(a1), "r"(a2), "r"(a3), "r"(b0), "r"(b1));
}

__device__ __forceinline__ void cp16(void* smem, const void* gmem) {
    unsigned saddr = (unsigned)__cvta_generic_to_shared(smem);
    asm volatile("cp.async.cg.shared.global [%0], [%1], 16;"
                 :: "r"(saddr), "l"(gmem));
}

// ---------------- edge dtype probe (one tiny launch) ----------------
__global__ void probe_kernel(const int* __restrict__ ei) {
    if (threadIdx.x == 0) {
        int all_zero = 1;
        for (int k = 1; k < 64; k += 2)
            if (ei[k] != 0) all_zero = 0;
        g_is64 = all_zero;
    }
}

// ---------------- W transpose: Wt[n][k] = W[k][n] ----------------
__global__ void transposeW_kernel(const float* __restrict__ W, float* __restrict__ Wt, int K) {
    int i = blockIdx.x * blockDim.x + threadIdx.x;
    if (i < K * 64) {
        int k = i >> 6, n = i & 63;
        Wt[n * K + k] = W[i];
    }
}

// ---------------- hierarchical scan ----------------
__global__ void scanA_kernel(int N) {
    __shared__ int red[256];
    int i = blockIdx.x * 256 + threadIdx.x;
    red[threadIdx.x] = (i < N) ? g_deg[i] : 0;
    __syncthreads();
    for (int off = 128; off; off >>= 1) {
        if (threadIdx.x < off) red[threadIdx.x] += red[threadIdx.x + off];
        __syncthreads();
    }
    if (threadIdx.x == 0) g_blocksum[blockIdx.x] = red[0];
}

__global__ void scanBC_kernel(int N) {
    __shared__ int ps[256];
    int b = blockIdx.x, t = threadIdx.x;

    int part = 0;
    for (int j = t; j < b; j += 256) part += g_blocksum[j];
    ps[t] = part;
    __syncthreads();
    for (int off = 128; off; off >>= 1) {
        if (t < off) ps[t] += ps[t + off];
        __syncthreads();
    }
    int offset = ps[0];
    __syncthreads();

    int i = b * 256 + t;
    int d = (i < N) ? g_deg[i] : 0;
    ps[t] = d;
    __syncthreads();
    for (int off = 1; off < 256; off <<= 1) {
        int v = (t >= off) ? ps[t - off] : 0;
        __syncthreads();
        ps[t] += v;
        __syncthreads();
    }
    int ex = offset + ps[t] - d;
    if (i < N) {
        g_rowptr[i]  = ex;
        g_rowptr2[i] = ex;
        g_deg[i]     = 0;
    }
    if (i == N - 1) g_rowptr[N] = ex + d;
}

__global__ void scatter_kernel(const int* __restrict__ ei, int E, int N) {
    int e = blockIdx.x * blockDim.x + threadIdx.x;
    if (e < E) {
        int dst, src;
        if (g_is64) { dst = ei[2 * (E + e)]; src = ei[2 * e]; }
        else        { dst = ei[E + e];       src = ei[e]; }
        if ((unsigned)dst >= (unsigned)N) return;
        int pos = atomicAdd(&g_rowptr2[dst], 1);
        if ((unsigned)pos < (unsigned)EMAX) g_csrc[pos] = src;
    }
}

// ---------------- tf32 tensor GEMM + attention logits (+optional count rider) ----------------
template <int K, int HEADS, bool DO_COUNT>
__global__ __launch_bounds__(256)
void gemm_att_kernel(const float* __restrict__ X, const float* __restrict__ Wt,
                     float* __restrict__ H,
                     const float* __restrict__ as, const float* __restrict__ ad,
                     float* __restrict__ es, float* __restrict__ ed, int N,
                     const int* __restrict__ ei, int E, int gemmBlocks)
{
    if (DO_COUNT && (int)blockIdx.x >= gemmBlocks) {
        int base   = ((int)blockIdx.x - gemmBlocks) * 256 + threadIdx.x;
        int stride = ((int)gridDim.x - gemmBlocks) * 256;
        if (g_is64) {
            for (int e = base; e < E; e += stride) {
                int dst = ei[2 * (E + e)];
                if ((unsigned)dst < (unsigned)N) atomicAdd(&g_deg[dst], 1);
            }
        } else {
            for (int e = base; e < E; e += stride) {
                int dst = ei[E + e];
                if ((unsigned)dst < (unsigned)N) atomicAdd(&g_deg[dst], 1);
            }
        }
        return;
    }

    __shared__ __align__(16) float xs[64 * 68];
    __shared__ __align__(16) float ws[64 * 68];

    const int n0   = blockIdx.x * 64;
    const int w    = threadIdx.x >> 5;
    const int lane = threadIdx.x & 31;
    const int r0   = (w >> 1) * 16;
    const int cb0  = (w & 1) * 32;
    const int gid  = lane >> 2;
    const int tig  = lane & 3;

    float acc[4][4];
#pragma unroll
    for (int nt = 0; nt < 4; nt++)
#pragma unroll
        for (int q = 0; q < 4; q++) acc[nt][q] = 0.f;

    for (int k0 = 0; k0 < K; k0 += 64) {
        const int len  = (K - k0 < 64) ? (K - k0) : 64;
        const int nseg = (len + 3) >> 2;

#pragma unroll
        for (int j = 0; j < 8; j++) {
            int idx = threadIdx.x + j * 256;
            int r   = (idx >> 4) & 63;
            int s   = idx & 15;
            bool isW = idx >= 1024;
            float* dstp = (isW ? ws : xs) + r * 68 + 4 * s;
            if (s < nseg) {
                if (isW) {
                    cp16(dstp, Wt + (size_t)r * K + k0 + 4 * s);
                } else {
                    int n = n0 + r;
                    if (n < N) cp16(dstp, X + (size_t)n * K + k0 + 4 * s);
                    else *reinterpret_cast<float4*>(dstp) = make_float4(0.f, 0.f, 0.f, 0.f);
                }
            } else {
                *reinterpret_cast<float4*>(dstp) = make_float4(0.f, 0.f, 0.f, 0.f);
            }
        }
        asm volatile("cp.async.commit_group;" ::: "memory");
        asm volatile("cp.async.wait_group 0;" ::: "memory");
        __syncthreads();

#pragma unroll
        for (int k8 = 0; k8 < 64; k8 += 8) {
            unsigned a0 = __float_as_uint(xs[(r0 + gid) * 68 + k8 + tig]);
            unsigned a1 = __float_as_uint(xs[(r0 + gid + 8) * 68 + k8 + tig]);
            unsigned a2 = __float_as_uint(xs[(r0 + gid) * 68 + k8 + tig + 4]);
            unsigned a3 = __float_as_uint(xs[(r0 + gid + 8) * 68 + k8 + tig + 4]);
#pragma unroll
            for (int nt = 0; nt < 4; nt++) {
                int nn = cb0 + nt * 8 + gid;
                unsigned b0 = __float_as_uint(ws[nn * 68 + k8 + tig]);
                unsigned b1 = __float_as_uint(ws[nn * 68 + k8 + tig + 4]);
                mma_tf32(acc[nt], a0, a1, a2, a3, b0, b1);
            }
        }
        __syncthreads();
    }

    float* ot = xs;
#pragma unroll
    for (int nt = 0; nt < 4; nt++) {
        int c = cb0 + nt * 8 + 2 * tig;
        ot[(r0 + gid) * 68 + c]         = acc[nt][0];
        ot[(r0 + gid) * 68 + c + 1]     = acc[nt][1];
        ot[(r0 + gid + 8) * 68 + c]     = acc[nt][2];
        ot[(r0 + gid + 8) * 68 + c + 1] = acc[nt][3];
    }
    __syncthreads();

#pragma unroll
    for (int j = 0; j < 4; j++) {
        int idx = threadIdx.x + j * 256;
        int r = idx >> 4, c4 = (idx & 15) * 4;
        int n = n0 + r;
        if (n < N) {
            float4 v = *reinterpret_cast<float4*>(&ot[r * 68 + c4]);
            *reinterpret_cast<float4*>(&H[(size_t)n * 64 + c4]) = v;
        }
    }

    if (HEADS == 8) {
        for (int p = threadIdx.x; p < 512; p += 256) {
            int r = p >> 3, hh = p & 7;
            int n = n0 + r;
            if (n < N) {
                float s = 0.f, d = 0.f;
#pragma unroll
                for (int k = 0; k < 8; k++) {
                    float v = ot[r * 68 + hh * 8 + k];
                    s += v * as[hh * 8 + k];
                    d += v * ad[hh * 8 + k];
                }
                es[n * 8 + hh] = s;
                ed[n * 8 + hh] = d;
            }
        }
    } else {
        int r = threadIdx.x >> 2, part = threadIdx.x & 3;
        float s = 0.f, d = 0.f;
#pragma unroll
        for (int k = 0; k < 16; k++) {
            float v = ot[r * 68 + part * 16 + k];
            s += v * as[part * 16 + k];
            d += v * ad[part * 16 + k];
        }
        s += __shfl_xor_sync(0xffffffffu, s, 1);
        s += __shfl_xor_sync(0xffffffffu, s, 2);
        d += __shfl_xor_sync(0xffffffffu, d, 1);
        d += __shfl_xor_sync(0xffffffffu, d, 2);
        int n = n0 + r;
        if (part == 0 && n < N) { es[n] = s; ed[n] = d; }
    }
}

// ---------------- layer-1 aggregation: 4 nodes/warp, lane = head ----------------
// Warp = 4 groups x 8 lanes. Group sub owns node n = 4*gw + sub; lane lx owns
// head lx (cols 8*lx..8*lx+7 = two float4). Per warp instruction: 4 edges.
__global__ void agg1_kernel(const float* __restrict__ H, const float* __restrict__ bias,
                            float* __restrict__ O, int N)
{
    int gw   = (blockIdx.x * blockDim.x + threadIdx.x) >> 5;
    int lane = threadIdx.x & 31;
    int sub  = lane >> 3;
    int lx   = lane & 7;
    int n    = gw * 4 + sub;
    bool valid = n < N;
    int nc   = valid ? n : N - 1;
    const float4* __restrict__ H4 = reinterpret_cast<const float4*>(H);

    float edv = g_ed1[nc * 8 + lx];

    // self-loop
    float w = __expf(lrelu(g_es1[nc * 8 + lx] + edv));
    float ws = w;
    float4 A = H4[nc * 16 + lx * 2];
    float4 B = H4[nc * 16 + lx * 2 + 1];
    A.x *= w; A.y *= w; A.z *= w; A.w *= w;
    B.x *= w; B.y *= w; B.z *= w; B.w *= w;

    int e0  = g_rowptr[nc];
    int deg = valid ? (g_rowptr[nc + 1] - e0) : 0;
    int dmax = deg;
    dmax = max(dmax, __shfl_xor_sync(0xffffffffu, dmax, 8));
    dmax = max(dmax, __shfl_xor_sync(0xffffffffu, dmax, 16));

    int i = 0;
    for (; i + 2 <= dmax; i += 2) {
        bool a0 = i < deg, a1 = i + 1 < deg;
        int s0 = a0 ? g_csrc[e0 + i]     : nc;
        int s1 = a1 ? g_csrc[e0 + i + 1] : nc;
        float t0 = g_es1[s0 * 8 + lx], t1 = g_es1[s1 * 8 + lx];
        float4 p0 = H4[s0 * 16 + lx * 2], q0 = H4[s0 * 16 + lx * 2 + 1];
        float4 p1 = H4[s1 * 16 + lx * 2], q1 = H4[s1 * 16 + lx * 2 + 1];
        float x0 = a0 ? __expf(lrelu(t0 + edv)) : 0.f;
        float x1 = a1 ? __expf(lrelu(t1 + edv)) : 0.f;
        ws += x0 + x1;
        A.x = fmaf(x0, p0.x, A.x); A.y = fmaf(x0, p0.y, A.y);
        A.z = fmaf(x0, p0.z, A.z); A.w = fmaf(x0, p0.w, A.w);
        B.x = fmaf(x0, q0.x, B.x); B.y = fmaf(x0, q0.y, B.y);
        B.z = fmaf(x0, q0.z, B.z); B.w = fmaf(x0, q0.w, B.w);
        A.x = fmaf(x1, p1.x, A.x); A.y = fmaf(x1, p1.y, A.y);
        A.z = fmaf(x1, p1.z, A.z); A.w = fmaf(x1, p1.w, A.w);
        B.x = fmaf(x1, q1.x, B.x); B.y = fmaf(x1, q1.y, B.y);
        B.z = fmaf(x1, q1.z, B.z); B.w = fmaf(x1, q1.w, B.w);
    }
    for (; i < dmax; i++) {
        bool a0 = i < deg;
        int s0 = a0 ? g_csrc[e0 + i] : nc;
        float t0 = g_es1[s0 * 8 + lx];
        float4 p0 = H4[s0 * 16 + lx * 2], q0 = H4[s0 * 16 + lx * 2 + 1];
        float x0 = a0 ? __expf(lrelu(t0 + edv)) : 0.f;
        ws += x0;
        A.x = fmaf(x0, p0.x, A.x); A.y = fmaf(x0, p0.y, A.y);
        A.z = fmaf(x0, p0.z, A.z); A.w = fmaf(x0, p0.w, A.w);
        B.x = fmaf(x0, q0.x, B.x); B.y = fmaf(x0, q0.y, B.y);
        B.z = fmaf(x0, q0.z, B.z); B.w = fmaf(x0, q0.w, B.w);
    }

    if (valid) {
        float inv = 1.f / ws;
        float4 b0 = reinterpret_cast<const float4*>(bias)[lx * 2];
        float4 b1 = reinterpret_cast<const float4*>(bias)[lx * 2 + 1];
        float o0 = A.x * inv + b0.x, o1 = A.y * inv + b0.y;
        float o2 = A.z * inv + b0.z, o3 = A.w * inv + b0.w;
        float o4 = B.x * inv + b1.x, o5 = B.y * inv + b1.y;
        float o6 = B.z * inv + b1.z, o7 = B.w * inv + b1.w;
        float4 r0, r1;
        r0.x = o0 > 0.f ? o0 : (__expf(o0) - 1.f);
        r0.y = o1 > 0.f ? o1 : (__expf(o1) - 1.f);
        r0.z = o2 > 0.f ? o2 : (__expf(o2) - 1.f);
        r0.w = o3 > 0.f ? o3 : (__expf(o3) - 1.f);
        r1.x = o4 > 0.f ? o4 : (__expf(o4) - 1.f);
        r1.y = o5 > 0.f ? o5 : (__expf(o5) - 1.f);
        r1.z = o6 > 0.f ? o6 : (__expf(o6) - 1.f);
        r1.w = o7 > 0.f ? o7 : (__expf(o7) - 1.f);
        reinterpret_cast<float4*>(O)[n * 16 + lx * 2]     = r0;
        reinterpret_cast<float4*>(O)[n * 16 + lx * 2 + 1] = r1;
    }
}

// ---------------- layer-2 aggregation + log_softmax: 4 nodes/warp ----------------
__global__ void agg2_kernel(const float* __restrict__ H, const float* __restrict__ bias,
                            float* __restrict__ O, int N)
{
    int gw   = (blockIdx.x * blockDim.x + threadIdx.x) >> 5;
    int lane = threadIdx.x & 31;
    int sub  = lane >> 3;
    int lx   = lane & 7;
    int n    = gw * 4 + sub;
    bool valid = n < N;
    int nc   = valid ? n : N - 1;
    const float4* __restrict__ H4 = reinterpret_cast<const float4*>(H);

    float edn = g_ed2[nc];

    float w = __expf(lrelu(g_es2[nc] + edn));   // self-loop
    float ws = w;
    float4 A = H4[nc * 16 + lx * 2];
    float4 B = H4[nc * 16 + lx * 2 + 1];
    A.x *= w; A.y *= w; A.z *= w; A.w *= w;
    B.x *= w; B.y *= w; B.z *= w; B.w *= w;

    int e0  = g_rowptr[nc];
    int deg = valid ? (g_rowptr[nc + 1] - e0) : 0;
    int dmax = deg;
    dmax = max(dmax, __shfl_xor_sync(0xffffffffu, dmax, 8));
    dmax = max(dmax, __shfl_xor_sync(0xffffffffu, dmax, 16));

    int i = 0;
    for (; i + 2 <= dmax; i += 2) {
        bool a0 = i < deg, a1 = i + 1 < deg;
        int s0 = a0 ? g_csrc[e0 + i]     : nc;
        int s1 = a1 ? g_csrc[e0 + i + 1] : nc;
        float t0 = g_es2[s0], t1 = g_es2[s1];
        float4 p0 = H4[s0 * 16 + lx * 2], q0 = H4[s0 * 16 + lx * 2 + 1];
        float4 p1 = H4[s1 * 16 + lx * 2], q1 = H4[s1 * 16 + lx * 2 + 1];
        float x0 = a0 ? __expf(lrelu(t0 + edn)) : 0.f;
        float x1 = a1 ? __expf(lrelu(t1 + edn)) : 0.f;
        ws += x0 + x1;
        A.x = fmaf(x0, p0.x, A.x); A.y = fmaf(x0, p0.y, A.y);
        A.z = fmaf(x0, p0.z, A.z); A.w = fmaf(x0, p0.w, A.w);
        B.x = fmaf(x0, q0.x, B.x); B.y = fmaf(x0, q0.y, B.y);
        B.z = fmaf(x0, q0.z, B.z); B.w = fmaf(x0, q0.w, B.w);
        A.x = fmaf(x1, p1.x, A.x); A.y = fmaf(x1, p1.y, A.y);
        A.z = fmaf(x1, p1.z, A.z); A.w = fmaf(x1, p1.w, A.w);
        B.x = fmaf(x1, q1.x, B.x); B.y = fmaf(x1, q1.y, B.y);
        B.z = fmaf(x1, q1.z, B.z); B.w = fmaf(x1, q1.w, B.w);
    }
    for (; i < dmax; i++) {
        bool a0 = i < deg;
        int s0 = a0 ? g_csrc[e0 + i] : nc;
        float t0 = g_es2[s0];
        float4 p0 = H4[s0 * 16 + lx * 2], q0 = H4[s0 * 16 + lx * 2 + 1];
        float x0 = a0 ? __expf(lrelu(t0 + edn)) : 0.f;
        ws += x0;
        A.x = fmaf(x0, p0.x, A.x); A.y = fmaf(x0, p0.y, A.y);
        A.z = fmaf(x0, p0.z, A.z); A.w = fmaf(x0, p0.w, A.w);
        B.x = fmaf(x0, q0.x, B.x); B.y = fmaf(x0, q0.y, B.y);
        B.z = fmaf(x0, q0.z, B.z); B.w = fmaf(x0, q0.w, B.w);
    }

    float inv = 1.f / ws;
    float4 b0 = reinterpret_cast<const float4*>(bias)[lx * 2];
    float4 b1 = reinterpret_cast<const float4*>(bias)[lx * 2 + 1];
    float v0 = A.x * inv + b0.x, v1 = A.y * inv + b0.y;
    float v2 = A.z * inv + b0.z, v3 = A.w * inv + b0.w;
    float v4 = B.x * inv + b1.x, v5 = B.y * inv + b1.y;
    float v6 = B.z * inv + b1.z, v7 = B.w * inv + b1.w;

    // log_softmax over 64 cols: local max/sum then 8-lane group reduce
    float mx = fmaxf(fmaxf(fmaxf(v0, v1), fmaxf(v2, v3)),
                     fmaxf(fmaxf(v4, v5), fmaxf(v6, v7)));
#pragma unroll
    for (int o = 1; o < 8; o <<= 1) mx = fmaxf(mx, __shfl_xor_sync(0xffffffffu, mx, o));
    float se = __expf(v0 - mx) + __expf(v1 - mx) + __expf(v2 - mx) + __expf(v3 - mx)
             + __expf(v4 - mx) + __expf(v5 - mx) + __expf(v6 - mx) + __expf(v7 - mx);
#pragma unroll
    for (int o = 1; o < 8; o <<= 1) se += __shfl_xor_sync(0xffffffffu, se, o);
    float lse = mx + logf(se);

    if (valid) {
        float4 r0 = make_float4(v0 - lse, v1 - lse, v2 - lse, v3 - lse);
        float4 r1 = make_float4(v4 - lse, v5 - lse, v6 - lse, v7 - lse);
        reinterpret_cast<float4*>(O)[n * 16 + lx * 2]     = r0;
        reinterpret_cast<float4*>(O)[n * 16 + lx * 2 + 1] = r1;
    }
}

// ---------------- launch ----------------
// Order: probe(0) tW1(1) tW2(2) gemm1+count(3) scanA(4) scanBC(5) scatter(6)
//        agg1(7) gemm2(8) agg2(9)  -> ncu idx-3 capture = gemm1 (control).
extern "C" void kernel_launch(void* const* d_in, const int* in_sizes, int n_in,
                              void* d_out, int out_size)
{
    const float* x   = (const float*)d_in[0];
    const int*   ei  = (const int*)d_in[1];    // int32 OR int64 (probed)
    const float* W1  = (const float*)d_in[2];
    const float* as1 = (const float*)d_in[3];
    const float* ad1 = (const float*)d_in[4];
    const float* b1  = (const float*)d_in[5];
    const float* W2  = (const float*)d_in[6];
    const float* as2 = (const float*)d_in[7];
    const float* ad2 = (const float*)d_in[8];
    const float* b2  = (const float*)d_in[9];

    const int N = in_sizes[0] / 300;
    const int E = in_sizes[1] / 2;
    float* out = (float*)d_out;

    void *ph1, *ph1o, *ph2, *pes1, *ped1, *pes2, *ped2, *pwt1, *pwt2;
    cudaGetSymbolAddress(&ph1,  g_h1);
    cudaGetSymbolAddress(&ph1o, g_h1o);
    cudaGetSymbolAddress(&ph2,  g_h2);
    cudaGetSymbolAddress(&pes1, g_es1);
    cudaGetSymbolAddress(&ped1, g_ed1);
    cudaGetSymbolAddress(&pes2, g_es2);
    cudaGetSymbolAddress(&ped2, g_ed2);
    cudaGetSymbolAddress(&pwt1, g_wt1);
    cudaGetSymbolAddress(&pwt2, g_wt2);
    float* h1  = (float*)ph1;
    float* h1o = (float*)ph1o;
    float* h2  = (float*)ph2;
    float* wt1 = (float*)pwt1;
    float* wt2 = (float*)pwt2;

    const int tb = 256;
    const int G  = (N + 63) / 64;      // 64-node gemm tiles
    const int SB = (N + 255) / 256;    // scan blocks
    const int CB = 512;                // count rider blocks
    const int AB = (N + 31) / 32;      // agg blocks (8 warps x 4 nodes = 32 nodes)

    probe_kernel     <<<1, 32>>>(ei);
    transposeW_kernel<<<(300 * 64 + tb - 1) / tb, tb>>>(W1, wt1, 300);
    transposeW_kernel<<<(64 * 64 + tb - 1) / tb, tb>>>(W2, wt2, 64);

    // layer-1 GEMM with degree-count rider (independent halves)
    gemm_att_kernel<300, 8, true><<<G + CB, 256>>>(x, wt1, h1, as1, ad1,
                                                   (float*)pes1, (float*)ped1, N,
                                                   ei, E, G);
    scanA_kernel  <<<SB, 256>>>(N);
    scanBC_kernel <<<SB, 256>>>(N);
    scatter_kernel<<<(E + tb - 1) / tb, tb>>>(ei, E, N);

    agg1_kernel<<<AB, tb>>>(h1, b1, h1o, N);

    // layer 2
    gemm_att_kernel<64, 1, false><<<G, 256>>>(h1o, wt2, h2, as2, ad2,
                                              (float*)pes2, (float*)ped2, N,
                                              ei, E, G);
    agg2_kernel<<<AB, tb>>>(h2, b2, out, N);
}